// round 1
// baseline (speedup 1.0000x reference)
#include <cuda_runtime.h>

// Problem constants
#define BB 4
#define CC 2048
#define NN 2304   // 48*48
#define DD 256

// Scratch: __device__ globals (no cudaMalloc allowed)
__device__ float g_q[2u * BB * DD * NN];        // qL, qR   [2][B][D][N]
__device__ float g_k[2u * BB * DD * NN];        // kR, kL   [2][B][D][N]
__device__ float g_attn[2ull * BB * NN * NN];   // scores/attn [2][B][N][N]

// ---------------------------------------------------------------------------
// Projection GEMM (NN layout + bias): O[d,n] = sum_c W[d,c] * X[c,n] + bias[d]
// W: [D,C] row-major, X: [C,N] row-major (per batch), O: [D,N]
// 128x128 tile, K-step 8, 8x8 per thread, 256 threads.
// ---------------------------------------------------------------------------
__global__ void __launch_bounds__(256) proj_kernel(
    const float* __restrict__ W, const float* __restrict__ bias,
    const float* __restrict__ Xb, float* __restrict__ Ob)
{
    const int b = blockIdx.z;
    const float* X = Xb + (size_t)b * CC * NN;
    float* O = Ob + (size_t)b * DD * NN;
    const int m0 = blockIdx.y << 7;
    const int n0 = blockIdx.x << 7;

    __shared__ float As[8][128];
    __shared__ float Bs[8][128];

    const int tid = threadIdx.x;
    const int tx = tid & 15, ty = tid >> 4;
    const int a_m = tid >> 1, a_k = (tid & 1) << 2;   // A: transpose load
    const int b_k = tid >> 5, b_n = (tid & 31) << 2;  // B: direct load

    float acc[8][8];
#pragma unroll
    for (int i = 0; i < 8; i++)
#pragma unroll
        for (int j = 0; j < 8; j++) acc[i][j] = 0.f;

    const float* Aptr = W + (size_t)(m0 + a_m) * CC + a_k;
    const float* Bptr = X + (size_t)b_k * NN + n0 + b_n;

    for (int k0 = 0; k0 < CC; k0 += 8) {
        float4 av = *(const float4*)(Aptr + k0);
        float4 bv = *(const float4*)(Bptr + (size_t)k0 * NN);
        As[a_k + 0][a_m] = av.x; As[a_k + 1][a_m] = av.y;
        As[a_k + 2][a_m] = av.z; As[a_k + 3][a_m] = av.w;
        *(float4*)&Bs[b_k][b_n] = bv;
        __syncthreads();
#pragma unroll
        for (int k = 0; k < 8; k++) {
            float a0[8], b0[8];
            *(float4*)(a0)     = *(const float4*)&As[k][ty << 3];
            *(float4*)(a0 + 4) = *(const float4*)&As[k][(ty << 3) + 4];
            *(float4*)(b0)     = *(const float4*)&Bs[k][tx << 3];
            *(float4*)(b0 + 4) = *(const float4*)&Bs[k][(tx << 3) + 4];
#pragma unroll
            for (int i = 0; i < 8; i++)
#pragma unroll
                for (int j = 0; j < 8; j++)
                    acc[i][j] = fmaf(a0[i], b0[j], acc[i][j]);
        }
        __syncthreads();
    }

#pragma unroll
    for (int i = 0; i < 8; i++) {
        const int d = m0 + (ty << 3) + i;
        const float bv = bias[d];
        float* orow = O + (size_t)d * NN + n0 + (tx << 3);
        float4 v0 = { acc[i][0] + bv, acc[i][1] + bv, acc[i][2] + bv, acc[i][3] + bv };
        float4 v1 = { acc[i][4] + bv, acc[i][5] + bv, acc[i][6] + bv, acc[i][7] + bv };
        *(float4*)(orow)     = v0;
        *(float4*)(orow + 4) = v1;
    }
}

// ---------------------------------------------------------------------------
// Scores GEMM (TN): S[i,j] = sum_d q[d,i] * k[d,j]
// q,k: [D,N] row-major per batch. S: [N,N].
// ---------------------------------------------------------------------------
__global__ void __launch_bounds__(256) scores_kernel(
    const float* __restrict__ qb, const float* __restrict__ kb,
    float* __restrict__ Sb)
{
    const int b = blockIdx.z;
    const float* q = qb + (size_t)b * DD * NN;
    const float* kk = kb + (size_t)b * DD * NN;
    float* S = Sb + (size_t)b * NN * NN;
    const int m0 = blockIdx.y << 7;
    const int n0 = blockIdx.x << 7;

    __shared__ float As[8][128];
    __shared__ float Bs[8][128];

    const int tid = threadIdx.x;
    const int tx = tid & 15, ty = tid >> 4;
    const int lk = tid >> 5, lc = (tid & 31) << 2;

    float acc[8][8];
#pragma unroll
    for (int i = 0; i < 8; i++)
#pragma unroll
        for (int j = 0; j < 8; j++) acc[i][j] = 0.f;

    const float* Ap = q + (size_t)lk * NN + m0 + lc;
    const float* Bp = kk + (size_t)lk * NN + n0 + lc;

    for (int k0 = 0; k0 < DD; k0 += 8) {
        *(float4*)&As[lk][lc] = *(const float4*)(Ap + (size_t)k0 * NN);
        *(float4*)&Bs[lk][lc] = *(const float4*)(Bp + (size_t)k0 * NN);
        __syncthreads();
#pragma unroll
        for (int k = 0; k < 8; k++) {
            float a0[8], b0[8];
            *(float4*)(a0)     = *(const float4*)&As[k][ty << 3];
            *(float4*)(a0 + 4) = *(const float4*)&As[k][(ty << 3) + 4];
            *(float4*)(b0)     = *(const float4*)&Bs[k][tx << 3];
            *(float4*)(b0 + 4) = *(const float4*)&Bs[k][(tx << 3) + 4];
#pragma unroll
            for (int i = 0; i < 8; i++)
#pragma unroll
                for (int j = 0; j < 8; j++)
                    acc[i][j] = fmaf(a0[i], b0[j], acc[i][j]);
        }
        __syncthreads();
    }

#pragma unroll
    for (int i = 0; i < 8; i++) {
        float* srow = S + (size_t)(m0 + (ty << 3) + i) * NN + n0 + (tx << 3);
        *(float4*)(srow)     = *(float4*)&acc[i][0];
        *(float4*)(srow + 4) = *(float4*)&acc[i][4];
    }
}

// ---------------------------------------------------------------------------
// Row softmax in place over rows of length NN. One block (256 thr) per row.
// NN = 2304 = 9 * 256 exactly.
// ---------------------------------------------------------------------------
__global__ void __launch_bounds__(256) softmax_kernel(float* __restrict__ Sb)
{
    float* S = Sb + (size_t)blockIdx.x * NN;
    const int tid = threadIdx.x;
    __shared__ float red[8];
    __shared__ float bcast;

    float v[9];
    float m = -3.4e38f;
#pragma unroll
    for (int j = 0; j < 9; j++) {
        v[j] = S[tid + (j << 8)];
        m = fmaxf(m, v[j]);
    }
#pragma unroll
    for (int o = 16; o; o >>= 1) m = fmaxf(m, __shfl_xor_sync(0xffffffffu, m, o));
    if ((tid & 31) == 0) red[tid >> 5] = m;
    __syncthreads();
    if (tid == 0) {
        float t = red[0];
#pragma unroll
        for (int i = 1; i < 8; i++) t = fmaxf(t, red[i]);
        bcast = t;
    }
    __syncthreads();
    m = bcast;

    float s = 0.f;
#pragma unroll
    for (int j = 0; j < 9; j++) {
        v[j] = expf(v[j] - m);
        s += v[j];
    }
#pragma unroll
    for (int o = 16; o; o >>= 1) s += __shfl_xor_sync(0xffffffffu, s, o);
    __syncthreads();   // red reuse hazard
    if ((tid & 31) == 0) red[tid >> 5] = s;
    __syncthreads();
    if (tid == 0) {
        float t = 0.f;
#pragma unroll
        for (int i = 0; i < 8; i++) t += red[i];
        bcast = 1.f / t;
    }
    __syncthreads();
    const float inv = bcast;
#pragma unroll
    for (int j = 0; j < 9; j++) S[tid + (j << 8)] = v[j] * inv;
}

// ---------------------------------------------------------------------------
// AV GEMM (NT): O[c,n] = sum_m V[c,m] * A[n,m]
// V: [C,N] row-major, A(attn): [N,N] row-major (both K=m contiguous).
// O base points at the weighted-half of the output; per-batch stride 2*C*N.
// ---------------------------------------------------------------------------
__global__ void __launch_bounds__(256) av_kernel(
    const float* __restrict__ Vb, const float* __restrict__ Ab,
    float* __restrict__ Ob)
{
    const int b = blockIdx.z;
    const float* V = Vb + (size_t)b * CC * NN;
    const float* A = Ab + (size_t)b * NN * NN;
    float* O = Ob + (size_t)b * 2 * CC * NN;
    const int m0 = blockIdx.y << 7;   // over C
    const int n0 = blockIdx.x << 7;   // over n

    __shared__ float As[8][128];
    __shared__ float Bs[8][128];

    const int tid = threadIdx.x;
    const int tx = tid & 15, ty = tid >> 4;
    const int r = tid >> 1, k4 = (tid & 1) << 2;

    float acc[8][8];
#pragma unroll
    for (int i = 0; i < 8; i++)
#pragma unroll
        for (int j = 0; j < 8; j++) acc[i][j] = 0.f;

    const float* Vp = V + (size_t)(m0 + r) * NN + k4;
    const float* Ap = A + (size_t)(n0 + r) * NN + k4;

    for (int k0 = 0; k0 < NN; k0 += 8) {
        float4 av = *(const float4*)(Vp + k0);
        float4 bv = *(const float4*)(Ap + k0);
        As[k4 + 0][r] = av.x; As[k4 + 1][r] = av.y;
        As[k4 + 2][r] = av.z; As[k4 + 3][r] = av.w;
        Bs[k4 + 0][r] = bv.x; Bs[k4 + 1][r] = bv.y;
        Bs[k4 + 2][r] = bv.z; Bs[k4 + 3][r] = bv.w;
        __syncthreads();
#pragma unroll
        for (int k = 0; k < 8; k++) {
            float a0[8], b0[8];
            *(float4*)(a0)     = *(const float4*)&As[k][ty << 3];
            *(float4*)(a0 + 4) = *(const float4*)&As[k][(ty << 3) + 4];
            *(float4*)(b0)     = *(const float4*)&Bs[k][tx << 3];
            *(float4*)(b0 + 4) = *(const float4*)&Bs[k][(tx << 3) + 4];
#pragma unroll
            for (int i = 0; i < 8; i++)
#pragma unroll
                for (int j = 0; j < 8; j++)
                    acc[i][j] = fmaf(a0[i], b0[j], acc[i][j]);
        }
        __syncthreads();
    }

#pragma unroll
    for (int i = 0; i < 8; i++) {
        float* orow = O + (size_t)(m0 + (ty << 3) + i) * NN + n0 + (tx << 3);
        *(float4*)(orow)     = *(float4*)&acc[i][0];
        *(float4*)(orow + 4) = *(float4*)&acc[i][4];
    }
}

// ---------------------------------------------------------------------------
// Copy raw features into the first C channels of each output tensor.
// ---------------------------------------------------------------------------
__global__ void __launch_bounds__(256) copy_kernel(
    const float4* __restrict__ L, const float4* __restrict__ R,
    float4* __restrict__ out)
{
    const size_t total = (size_t)BB * CC * NN / 4;
    size_t i = (size_t)blockIdx.x * 256 + threadIdx.x;
    if (i >= total) return;
    const size_t per_b = (size_t)CC * NN / 4;
    const size_t b = i / per_b;
    const size_t rem = i - b * per_b;
    const size_t dst = b * ((size_t)2 * CC * NN / 4) + rem;
    out[dst] = L[i];
    out[dst + (size_t)BB * 2 * CC * NN / 4] = R[i];
}

// ---------------------------------------------------------------------------
extern "C" void kernel_launch(void* const* d_in, const int* in_sizes, int n_in,
                              void* d_out, int out_size)
{
    const float* L  = (const float*)d_in[0];
    const float* R  = (const float*)d_in[1];
    const float* wq = (const float*)d_in[2];
    const float* bq = (const float*)d_in[3];
    const float* wr = (const float*)d_in[4];
    const float* br = (const float*)d_in[5];
    float* out = (float*)d_out;

    float *q, *k, *attn;
    cudaGetSymbolAddress((void**)&q, g_q);
    cudaGetSymbolAddress((void**)&k, g_k);
    cudaGetSymbolAddress((void**)&attn, g_attn);

    const size_t qk_stride = (size_t)BB * DD * NN;
    const size_t at_stride = (size_t)BB * NN * NN;
    const size_t half = (size_t)CC * NN;               // offset to weighted half (per batch handled in kernel)
    const size_t outR = (size_t)BB * 2 * CC * NN;      // start of right_attended

    dim3 gproj(NN / 128, DD / 128, BB);
    proj_kernel<<<gproj, 256>>>(wq, bq, L, q);                 // qL
    proj_kernel<<<gproj, 256>>>(wr, br, R, k);                 // kR
    proj_kernel<<<gproj, 256>>>(wq, bq, R, q + qk_stride);     // qR
    proj_kernel<<<gproj, 256>>>(wr, br, L, k + qk_stride);     // kL

    dim3 gsc(NN / 128, NN / 128, BB);
    scores_kernel<<<gsc, 256>>>(q, k, attn);                           // S1 = qL . kR
    scores_kernel<<<gsc, 256>>>(q + qk_stride, k + qk_stride, attn + at_stride);  // S2 = qR . kL

    softmax_kernel<<<BB * NN, 256>>>(attn);
    softmax_kernel<<<BB * NN, 256>>>(attn + at_stride);

    dim3 gav(NN / 128, CC / 128, BB);
    av_kernel<<<gav, 256>>>(R, attn, out + half);                  // weighted_r -> left_attended[C:2C]
    av_kernel<<<gav, 256>>>(L, attn + at_stride, out + outR + half); // weighted_l -> right_attended[C:2C]

    const size_t ncpy = (size_t)BB * CC * NN / 4;
    copy_kernel<<<(unsigned)((ncpy + 255) / 256), 256>>>(
        (const float4*)L, (const float4*)R, (float4*)out);
}

// round 3
// speedup vs baseline: 2.4869x; 2.4869x over previous
#include <cuda_runtime.h>
#include <cstdint>

#define BB 4
#define CC 2048
#define NN 2304   // 48*48
#define DD 256

// ---------------------------------------------------------------------------
// Scratch (__device__ globals; no cudaMalloc allowed)
// q,k stored [dir][b][n][d] (K-major in d for the scores GEMM)
// ---------------------------------------------------------------------------
__device__ float g_q[2ull * BB * NN * DD];
__device__ float g_k[2ull * BB * NN * DD];
__device__ float g_attn[2ull * BB * NN * NN];

// ---------------------------------------------------------------------------
// helpers
// ---------------------------------------------------------------------------
__device__ __forceinline__ uint32_t smem_u32(const void* p) {
    uint32_t a;
    asm("{ .reg .u64 t; cvta.to.shared.u64 t, %1; cvt.u32.u64 %0, t; }" : "=r"(a) : "l"(p));
    return a;
}

__device__ __forceinline__ void cp16(uint32_t dst, const void* src) {
    asm volatile("cp.async.cg.shared.global [%0], [%1], 16;" :: "r"(dst), "l"(src));
}
#define CP_COMMIT() asm volatile("cp.async.commit_group;")
#define CP_WAIT(n)  asm volatile("cp.async.wait_group %0;" :: "n"(n))

__device__ __forceinline__ uint32_t f2tf32(float x) {
    uint32_t u;
    asm("cvt.rna.tf32.f32 %0, %1;" : "=r"(u) : "f"(x));
    return u;
}

__device__ __forceinline__ void mma8(float* c, const uint32_t* a, const uint32_t* b) {
    asm volatile(
        "mma.sync.aligned.m16n8k8.row.col.f32.tf32.tf32.f32 "
        "{%0,%1,%2,%3}, {%4,%5,%6,%7}, {%8,%9}, {%0,%1,%2,%3};"
        : "+f"(c[0]), "+f"(c[1]), "+f"(c[2]), "+f"(c[3])
        : "r"(a[0]), "r"(a[1]), "r"(a[2]), "r"(a[3]), "r"(b[0]), "r"(b[1]));
}

// ---------------------------------------------------------------------------
// Generic CTA-tile GEMM: C[m0..+128, n0..+128] (+)= A * B^T
//   A: !TRANSA: A[m][k] at A + m*lda + k   (k contiguous)
//       TRANSA: A[k][m] at A + k*lda + m   (m contiguous; proj X)
//   B: B[n][k] at B + n*ldb + k            (k contiguous)
//   C: C[m][n] at C + m*ldc + n
// SPLIT: 1 = single-pass tf32, 3 = tf32x3 (hi/lo split, near-fp32)
// 256 threads, 8 warps (4x2), warp tile 32x64, k-tile 16.
// ---------------------------------------------------------------------------
#define ASTRIDE 20   // floats per smem row (padding kills bank conflicts)

template <int SPLIT, bool TRANSA, bool HASBIAS>
__device__ __forceinline__ void gemm_dev(
    const float* __restrict__ A, const float* __restrict__ B,
    const float* __restrict__ bias, float* __restrict__ C,
    int lda, int ldb, int ldc, int K, int m0, int n0)
{
    __shared__ float As[2][128 * ASTRIDE];
    __shared__ float Bs[2][128 * ASTRIDE];

    const int tid = threadIdx.x, wid = tid >> 5, lane = tid & 31;
    const int wm = wid >> 1, wn = wid & 1;
    const int gid = lane >> 2, tig = lane & 3;

    float acc[2][8][4];
#pragma unroll
    for (int i = 0; i < 2; i++)
#pragma unroll
        for (int j = 0; j < 8; j++)
#pragma unroll
            for (int e = 0; e < 4; e++) acc[i][j][e] = 0.f;

    const int KT = K >> 4;

    // ---- tile loaders -----------------------------------------------------
    auto load_tile = [&](int buf, int kt) {
        // B: 128 rows x 16 k-floats via cp.async
#pragma unroll
        for (int i = 0; i < 2; i++) {
            int idx = tid + (i << 8);
            int row = idx >> 2, g = idx & 3;
            cp16(smem_u32(&Bs[buf][row * ASTRIDE + (g << 2)]),
                 B + (size_t)(n0 + row) * ldb + (kt << 4) + (g << 2));
        }
        if (!TRANSA) {
#pragma unroll
            for (int i = 0; i < 2; i++) {
                int idx = tid + (i << 8);
                int row = idx >> 2, g = idx & 3;
                cp16(smem_u32(&As[buf][row * ASTRIDE + (g << 2)]),
                     A + (size_t)(m0 + row) * lda + (kt << 4) + (g << 2));
            }
        } else {
            // transpose X[c][n] -> As[n][c]
            const int n = tid & 127, cg = tid >> 7;
#pragma unroll
            for (int i = 0; i < 2; i++) {
                int c0 = (cg + 2 * i) << 2;
                const float* s = A + (size_t)((kt << 4) + c0) * lda + m0 + n;
                float4 v;
                v.x = s[0]; v.y = s[lda]; v.z = s[2 * lda]; v.w = s[3 * lda];
                *(float4*)&As[buf][n * ASTRIDE + c0] = v;
            }
        }
    };

    auto compute = [&](int buf) {
#pragma unroll
        for (int ks = 0; ks < 2; ks++) {
            const int kb = ks << 3;
            uint32_t ah[2][4], al[2][4];
#pragma unroll
            for (int mf = 0; mf < 2; mf++) {
                const int r0 = (wm << 5) + (mf << 4) + gid, r1 = r0 + 8;
                float raw[4];
                raw[0] = As[buf][r0 * ASTRIDE + kb + tig];
                raw[1] = As[buf][r1 * ASTRIDE + kb + tig];
                raw[2] = As[buf][r0 * ASTRIDE + kb + tig + 4];
                raw[3] = As[buf][r1 * ASTRIDE + kb + tig + 4];
#pragma unroll
                for (int e = 0; e < 4; e++) {
                    ah[mf][e] = f2tf32(raw[e]);
                    if (SPLIT == 3)
                        al[mf][e] = f2tf32(raw[e] - __uint_as_float(ah[mf][e]));
                }
            }
            uint32_t bh[8][2], bl[8][2];
#pragma unroll
            for (int nf = 0; nf < 8; nf++) {
                const int n = (wn << 6) + (nf << 3) + gid;
                float r0 = Bs[buf][n * ASTRIDE + kb + tig];
                float r1 = Bs[buf][n * ASTRIDE + kb + tig + 4];
                bh[nf][0] = f2tf32(r0);
                bh[nf][1] = f2tf32(r1);
                if (SPLIT == 3) {
                    bl[nf][0] = f2tf32(r0 - __uint_as_float(bh[nf][0]));
                    bl[nf][1] = f2tf32(r1 - __uint_as_float(bh[nf][1]));
                }
            }
#pragma unroll
            for (int mf = 0; mf < 2; mf++)
#pragma unroll
                for (int nf = 0; nf < 8; nf++) {
                    mma8(acc[mf][nf], ah[mf], bh[nf]);
                    if (SPLIT == 3) {
                        mma8(acc[mf][nf], ah[mf], bl[nf]);
                        mma8(acc[mf][nf], al[mf], bh[nf]);
                    }
                }
        }
    };

    // ---- mainloop (double buffered) --------------------------------------
    load_tile(0, 0);
    CP_COMMIT();
    for (int kt = 0; kt < KT; kt++) {
        if (kt + 1 < KT) {
            load_tile((kt + 1) & 1, kt + 1);
            CP_COMMIT();
            CP_WAIT(1);
        } else {
            CP_WAIT(0);
        }
        __syncthreads();
        compute(kt & 1);
        __syncthreads();
    }

    // ---- epilogue ---------------------------------------------------------
#pragma unroll
    for (int mf = 0; mf < 2; mf++) {
        const int r = m0 + (wm << 5) + (mf << 4) + gid;
#pragma unroll
        for (int nf = 0; nf < 8; nf++) {
            const int col = n0 + (wn << 6) + (nf << 3) + (tig << 1);
            float2 v0 = { acc[mf][nf][0], acc[mf][nf][1] };
            float2 v1 = { acc[mf][nf][2], acc[mf][nf][3] };
            if (HASBIAS) {
                const float b0 = bias[col], b1 = bias[col + 1];
                v0.x += b0; v0.y += b1; v1.x += b0; v1.y += b1;
            }
            *(float2*)&C[(size_t)r * ldc + col] = v0;
            *(float2*)&C[(size_t)(r + 8) * ldc + col] = v1;
        }
    }
}

// ---------------------------------------------------------------------------
// proj: q'[n,d] = sum_c X[c,n] * W[d,c] + bias[d]   (tf32x3)
// grid: x = d-tile (2), y = n-tile (18), z = pidx*4 + b (16)
// ---------------------------------------------------------------------------
__global__ void __launch_bounds__(256) proj_mma_kernel(
    const float* __restrict__ L, const float* __restrict__ R,
    const float* __restrict__ wq, const float* __restrict__ bq,
    const float* __restrict__ wr, const float* __restrict__ br,
    float* __restrict__ qb, float* __restrict__ kb)
{
    const int z = blockIdx.z, pidx = z >> 2, b = z & 3;
    const float* X = ((pidx == 0) || (pidx == 3)) ? L : R;
    X += (size_t)b * CC * NN;
    const float* W    = (pidx & 1) ? wr : wq;
    const float* bias = (pidx & 1) ? br : bq;
    float* outp = ((pidx & 1) ? kb : qb) + ((size_t)(pidx >> 1) * BB + b) * NN * DD;

    gemm_dev<3, true, true>(X, W, bias, outp, NN, CC, DD, CC,
                            blockIdx.y << 7, blockIdx.x << 7);
}

// ---------------------------------------------------------------------------
// scores: S[i,j] = sum_d q'[i,d] * k'[j,d]   (tf32x3)
// grid: x = j-tile (18), y = i-tile (18), z = dir*4 + b (8)
// ---------------------------------------------------------------------------
__global__ void __launch_bounds__(256) scores_mma_kernel(
    const float* __restrict__ qb, const float* __restrict__ kb,
    float* __restrict__ Sb)
{
    const size_t z = blockIdx.z;
    gemm_dev<3, false, false>(qb + z * NN * DD, kb + z * NN * DD, nullptr,
                              Sb + z * NN * NN, DD, DD, NN, DD,
                              blockIdx.y << 7, blockIdx.x << 7);
}

// ---------------------------------------------------------------------------
// av: O[c,n] = sum_m V[c,m] * attn[n,m]   (single-pass tf32, rna)
// grid: x = n-tile (18), y = c-tile (16), z = dir*4 + b (8)
// ---------------------------------------------------------------------------
__global__ void __launch_bounds__(256) av_mma_kernel(
    const float* __restrict__ L, const float* __restrict__ R,
    const float* __restrict__ attnb, float* __restrict__ out)
{
    const int z = blockIdx.z, dir = z >> 2, b = z & 3;
    const float* V = (dir ? L : R) + (size_t)b * CC * NN;
    const float* A = attnb + (size_t)z * NN * NN;
    float* outb = out + ((size_t)(dir ? BB : 0) + b) * 2 * CC * NN + (size_t)CC * NN;

    gemm_dev<1, false, false>(V, A, nullptr, outb, NN, NN, NN, NN,
                              blockIdx.y << 7, blockIdx.x << 7);
}

// ---------------------------------------------------------------------------
// Row softmax in place over rows of length NN. One block (256 thr) per row.
// ---------------------------------------------------------------------------
__global__ void __launch_bounds__(256) softmax_kernel(float* __restrict__ Sb)
{
    float* S = Sb + (size_t)blockIdx.x * NN;
    const int tid = threadIdx.x;
    __shared__ float red[8];
    __shared__ float bcast;

    float v[9];
    float m = -3.4e38f;
#pragma unroll
    for (int j = 0; j < 9; j++) {
        v[j] = S[tid + (j << 8)];
        m = fmaxf(m, v[j]);
    }
#pragma unroll
    for (int o = 16; o; o >>= 1) m = fmaxf(m, __shfl_xor_sync(0xffffffffu, m, o));
    if ((tid & 31) == 0) red[tid >> 5] = m;
    __syncthreads();
    if (tid == 0) {
        float t = red[0];
#pragma unroll
        for (int i = 1; i < 8; i++) t = fmaxf(t, red[i]);
        bcast = t;
    }
    __syncthreads();
    m = bcast;

    float s = 0.f;
#pragma unroll
    for (int j = 0; j < 9; j++) {
        v[j] = expf(v[j] - m);
        s += v[j];
    }
#pragma unroll
    for (int o = 16; o; o >>= 1) s += __shfl_xor_sync(0xffffffffu, s, o);
    __syncthreads();
    if ((tid & 31) == 0) red[tid >> 5] = s;
    __syncthreads();
    if (tid == 0) {
        float t = 0.f;
#pragma unroll
        for (int i = 0; i < 8; i++) t += red[i];
        bcast = 1.f / t;
    }
    __syncthreads();
    const float inv = bcast;
#pragma unroll
    for (int j = 0; j < 9; j++) S[tid + (j << 8)] = v[j] * inv;
}

// ---------------------------------------------------------------------------
// Copy raw features into the first C channels of each output tensor.
// ---------------------------------------------------------------------------
__global__ void __launch_bounds__(256) copy_kernel(
    const float4* __restrict__ L, const float4* __restrict__ R,
    float4* __restrict__ out)
{
    const size_t total = (size_t)BB * CC * NN / 4;
    size_t i = (size_t)blockIdx.x * 256 + threadIdx.x;
    if (i >= total) return;
    const size_t per_b = (size_t)CC * NN / 4;
    const size_t b = i / per_b;
    const size_t rem = i - b * per_b;
    const size_t dst = b * ((size_t)2 * CC * NN / 4) + rem;
    out[dst] = L[i];
    out[dst + (size_t)BB * 2 * CC * NN / 4] = R[i];
}

// ---------------------------------------------------------------------------
extern "C" void kernel_launch(void* const* d_in, const int* in_sizes, int n_in,
                              void* d_out, int out_size)
{
    const float* L  = (const float*)d_in[0];
    const float* R  = (const float*)d_in[1];
    const float* wq = (const float*)d_in[2];
    const float* bq = (const float*)d_in[3];
    const float* wr = (const float*)d_in[4];
    const float* br = (const float*)d_in[5];
    float* out = (float*)d_out;

    float *q, *k, *attn;
    cudaGetSymbolAddress((void**)&q, g_q);
    cudaGetSymbolAddress((void**)&k, g_k);
    cudaGetSymbolAddress((void**)&attn, g_attn);

    proj_mma_kernel<<<dim3(DD / 128, NN / 128, 16), 256>>>(L, R, wq, bq, wr, br, q, k);
    scores_mma_kernel<<<dim3(NN / 128, NN / 128, 8), 256>>>(q, k, attn);
    softmax_kernel<<<2 * BB * NN, 256>>>(attn);
    av_mma_kernel<<<dim3(NN / 128, CC / 128, 8), 256>>>(L, R, attn, out);

    const size_t ncpy = (size_t)BB * CC * NN / 4;
    copy_kernel<<<(unsigned)((ncpy + 255) / 256), 256>>>(
        (const float4*)L, (const float4*)R, (float4*)out);
}

// round 4
// speedup vs baseline: 2.5254x; 1.0155x over previous
#include <cuda_runtime.h>
#include <cstdint>

#define BB 4
#define CC 2048
#define NN 2304   // 48*48
#define DD 256

// ---------------------------------------------------------------------------
// Scratch (__device__ globals; no cudaMalloc allowed)
// q,k stored split (hi/lo tf32 components) [dir][b][n][d]
// ---------------------------------------------------------------------------
__device__ float g_qh[2ull * BB * NN * DD];
__device__ float g_ql[2ull * BB * NN * DD];
__device__ float g_kh[2ull * BB * NN * DD];
__device__ float g_kl[2ull * BB * NN * DD];
__device__ float g_attn[2ull * BB * NN * NN];

// ---------------------------------------------------------------------------
// helpers
// ---------------------------------------------------------------------------
__device__ __forceinline__ uint32_t smem_u32(const void* p) {
    uint32_t a;
    asm("{ .reg .u64 t; cvta.to.shared.u64 t, %1; cvt.u32.u64 %0, t; }" : "=r"(a) : "l"(p));
    return a;
}

__device__ __forceinline__ void cp16(uint32_t dst, const void* src) {
    asm volatile("cp.async.cg.shared.global [%0], [%1], 16;" :: "r"(dst), "l"(src));
}
#define CP_COMMIT() asm volatile("cp.async.commit_group;")
#define CP_WAIT(n)  asm volatile("cp.async.wait_group %0;" :: "n"(n))

__device__ __forceinline__ uint32_t f2tf32(float x) {
    uint32_t u;
    asm("cvt.rna.tf32.f32 %0, %1;" : "=r"(u) : "f"(x));
    return u;
}

__device__ __forceinline__ void mma8(float* c, const uint32_t* a, const uint32_t* b) {
    asm volatile(
        "mma.sync.aligned.m16n8k8.row.col.f32.tf32.tf32.f32 "
        "{%0,%1,%2,%3}, {%4,%5,%6,%7}, {%8,%9}, {%0,%1,%2,%3};"
        : "+f"(c[0]), "+f"(c[1]), "+f"(c[2]), "+f"(c[3])
        : "r"(a[0]), "r"(a[1]), "r"(a[2]), "r"(a[3]), "r"(b[0]), "r"(b[1]));
}

#define ASTRIDE 20   // floats per smem row (16 data + 4 pad; conflict-free LDS)

// ---------------------------------------------------------------------------
// proj: q'[n,d] = sum_c X[c,n] * W[d,c] + bias[d]   (tf32x3, on-the-fly cvt)
// Epilogue splits result into hi/lo tf32 components for the scores kernel.
// grid: x = d-tile (2), y = n-tile (18), z = pidx*4 + b (16)
// ---------------------------------------------------------------------------
__global__ void __launch_bounds__(256) proj_mma_kernel(
    const float* __restrict__ L, const float* __restrict__ R,
    const float* __restrict__ wq, const float* __restrict__ bq,
    const float* __restrict__ wr, const float* __restrict__ br,
    float* __restrict__ qh_g, float* __restrict__ ql_g,
    float* __restrict__ kh_g, float* __restrict__ kl_g)
{
    __shared__ float As[2][128 * ASTRIDE];
    __shared__ float Bs[2][128 * ASTRIDE];

    const int z = blockIdx.z, pidx = z >> 2, b = z & 3;
    const float* X = ((pidx == 0) || (pidx == 3)) ? L : R;
    X += (size_t)b * CC * NN;
    const float* W    = (pidx & 1) ? wr : wq;
    const float* bias = (pidx & 1) ? br : bq;
    float* oh = ((pidx & 1) ? kh_g : qh_g) + ((size_t)(pidx >> 1) * BB + b) * NN * DD;
    float* ol = ((pidx & 1) ? kl_g : ql_g) + ((size_t)(pidx >> 1) * BB + b) * NN * DD;

    const int m0 = blockIdx.y << 7;   // over n
    const int n0 = blockIdx.x << 7;   // over d

    const int tid = threadIdx.x, wid = tid >> 5, lane = tid & 31;
    const int wm = wid >> 1, wn = wid & 1;
    const int gid = lane >> 2, tig = lane & 3;

    float acc[2][8][4];
#pragma unroll
    for (int i = 0; i < 2; i++)
#pragma unroll
        for (int j = 0; j < 8; j++)
#pragma unroll
            for (int e = 0; e < 4; e++) acc[i][j][e] = 0.f;

    auto load_tile = [&](int buf, int kt) {
        // B = W rows (d), k contiguous
#pragma unroll
        for (int i = 0; i < 2; i++) {
            int idx = tid + (i << 8);
            int row = idx >> 2, g = idx & 3;
            cp16(smem_u32(&Bs[buf][row * ASTRIDE + (g << 2)]),
                 W + (size_t)(n0 + row) * CC + (kt << 4) + (g << 2));
        }
        // A = X transpose: X[c][n] -> As[n][c]
        const int n = tid & 127, cg = tid >> 7;
#pragma unroll
        for (int i = 0; i < 2; i++) {
            int c0 = (cg + 2 * i) << 2;
            const float* s = X + (size_t)((kt << 4) + c0) * NN + m0 + n;
            float4 v;
            v.x = s[0]; v.y = s[NN]; v.z = s[2 * NN]; v.w = s[3 * NN];
            *(float4*)&As[buf][n * ASTRIDE + c0] = v;
        }
    };

    auto compute = [&](int buf) {
#pragma unroll
        for (int ks = 0; ks < 2; ks++) {
            const int kb = ks << 3;
            uint32_t ah[2][4], al[2][4];
#pragma unroll
            for (int mf = 0; mf < 2; mf++) {
                const int r0 = (wm << 5) + (mf << 4) + gid, r1 = r0 + 8;
                float raw[4];
                raw[0] = As[buf][r0 * ASTRIDE + kb + tig];
                raw[1] = As[buf][r1 * ASTRIDE + kb + tig];
                raw[2] = As[buf][r0 * ASTRIDE + kb + tig + 4];
                raw[3] = As[buf][r1 * ASTRIDE + kb + tig + 4];
#pragma unroll
                for (int e = 0; e < 4; e++) {
                    ah[mf][e] = f2tf32(raw[e]);
                    al[mf][e] = f2tf32(raw[e] - __uint_as_float(ah[mf][e]));
                }
            }
            uint32_t bh[8][2], bl[8][2];
#pragma unroll
            for (int nf = 0; nf < 8; nf++) {
                const int n = (wn << 6) + (nf << 3) + gid;
                float r0 = Bs[buf][n * ASTRIDE + kb + tig];
                float r1 = Bs[buf][n * ASTRIDE + kb + tig + 4];
                bh[nf][0] = f2tf32(r0);
                bh[nf][1] = f2tf32(r1);
                bl[nf][0] = f2tf32(r0 - __uint_as_float(bh[nf][0]));
                bl[nf][1] = f2tf32(r1 - __uint_as_float(bh[nf][1]));
            }
#pragma unroll
            for (int mf = 0; mf < 2; mf++)
#pragma unroll
                for (int nf = 0; nf < 8; nf++) {
                    mma8(acc[mf][nf], ah[mf], bh[nf]);
                    mma8(acc[mf][nf], ah[mf], bl[nf]);
                    mma8(acc[mf][nf], al[mf], bh[nf]);
                }
        }
    };

    const int KT = CC >> 4;  // 128
    load_tile(0, 0);
    CP_COMMIT();
    for (int kt = 0; kt < KT; kt++) {
        if (kt + 1 < KT) {
            load_tile((kt + 1) & 1, kt + 1);
            CP_COMMIT();
            CP_WAIT(1);
        } else {
            CP_WAIT(0);
        }
        __syncthreads();
        compute(kt & 1);
        __syncthreads();
    }

    // epilogue: add bias, split into hi/lo tf32
#pragma unroll
    for (int mf = 0; mf < 2; mf++) {
        const int r = m0 + (wm << 5) + (mf << 4) + gid;
#pragma unroll
        for (int nf = 0; nf < 8; nf++) {
            const int col = n0 + (wn << 6) + (nf << 3) + (tig << 1);
            const float b0 = bias[col], b1 = bias[col + 1];
            float v[4] = { acc[mf][nf][0] + b0, acc[mf][nf][1] + b1,
                           acc[mf][nf][2] + b0, acc[mf][nf][3] + b1 };
            float hi[4], lo[4];
#pragma unroll
            for (int e = 0; e < 4; e++) {
                hi[e] = __uint_as_float(f2tf32(v[e]));
                lo[e] = __uint_as_float(f2tf32(v[e] - hi[e]));
            }
            *(float2*)&oh[(size_t)r * DD + col]       = make_float2(hi[0], hi[1]);
            *(float2*)&oh[(size_t)(r + 8) * DD + col] = make_float2(hi[2], hi[3]);
            *(float2*)&ol[(size_t)r * DD + col]       = make_float2(lo[0], lo[1]);
            *(float2*)&ol[(size_t)(r + 8) * DD + col] = make_float2(lo[2], lo[3]);
        }
    }
}

// ---------------------------------------------------------------------------
// scores: S[i,j] = qh.kh + qh.kl + ql.kh  (pure-MMA mainloop, operands pre-split)
// CTA 128x128, 8 warps (4m x 2n), warp tile 32x64. Dyn smem 80KB.
// grid: x = j-tile (18), y = i-tile (18), z = dir*4 + b (8)
// ---------------------------------------------------------------------------
__global__ void __launch_bounds__(256) scores_mma_kernel(
    const float* __restrict__ qh_g, const float* __restrict__ ql_g,
    const float* __restrict__ kh_g, const float* __restrict__ kl_g,
    float* __restrict__ Sb)
{
    extern __shared__ float sm[];
    const size_t z = blockIdx.z;
    const float* qh = qh_g + z * NN * DD;
    const float* ql = ql_g + z * NN * DD;
    const float* kh = kh_g + z * NN * DD;
    const float* kl = kl_g + z * NN * DD;
    float* S = Sb + z * NN * NN;
    const int i0 = blockIdx.y << 7;
    const int j0 = blockIdx.x << 7;

    const int tid = threadIdx.x, wid = tid >> 5, lane = tid & 31;
    const int wm = wid >> 1, wn = wid & 1;
    const int gid = lane >> 2, tig = lane & 3;

    float acc[2][8][4];
#pragma unroll
    for (int i = 0; i < 2; i++)
#pragma unroll
        for (int j = 0; j < 8; j++)
#pragma unroll
            for (int e = 0; e < 4; e++) acc[i][j][e] = 0.f;

    // stage layout: [Ah | Al | Bh | Bl] each 2560 floats -> 10240 floats/stage
    auto load_tile = [&](int s, int kt) {
        float* p = sm + s * 10240;
        const float* srcs[4] = { qh + (size_t)i0 * DD, ql + (size_t)i0 * DD,
                                 kh + (size_t)j0 * DD, kl + (size_t)j0 * DD };
#pragma unroll
        for (int a = 0; a < 4; a++) {
#pragma unroll
            for (int i = 0; i < 2; i++) {
                int idx = tid + (i << 8);
                int row = idx >> 2, g = idx & 3;
                cp16(smem_u32(&p[a * 2560 + row * ASTRIDE + (g << 2)]),
                     srcs[a] + (size_t)row * DD + (kt << 4) + (g << 2));
            }
        }
    };

    auto compute = [&](int s) {
        const float* Ah = sm + s * 10240;
        const float* Al = Ah + 2560;
        const float* Bh = Ah + 5120;
        const float* Bl = Ah + 7680;
#pragma unroll
        for (int ks = 0; ks < 2; ks++) {
            const int kb = ks << 3;
            uint32_t ah[2][4], al2[2][4];
#pragma unroll
            for (int mf = 0; mf < 2; mf++) {
                const int r0 = (wm << 5) + (mf << 4) + gid, r1 = r0 + 8;
                ah[mf][0]  = __float_as_uint(Ah[r0 * ASTRIDE + kb + tig]);
                ah[mf][1]  = __float_as_uint(Ah[r1 * ASTRIDE + kb + tig]);
                ah[mf][2]  = __float_as_uint(Ah[r0 * ASTRIDE + kb + tig + 4]);
                ah[mf][3]  = __float_as_uint(Ah[r1 * ASTRIDE + kb + tig + 4]);
                al2[mf][0] = __float_as_uint(Al[r0 * ASTRIDE + kb + tig]);
                al2[mf][1] = __float_as_uint(Al[r1 * ASTRIDE + kb + tig]);
                al2[mf][2] = __float_as_uint(Al[r0 * ASTRIDE + kb + tig + 4]);
                al2[mf][3] = __float_as_uint(Al[r1 * ASTRIDE + kb + tig + 4]);
            }
            uint32_t bh[8][2], bl2[8][2];
#pragma unroll
            for (int nf = 0; nf < 8; nf++) {
                const int n = (wn << 6) + (nf << 3) + gid;
                bh[nf][0]  = __float_as_uint(Bh[n * ASTRIDE + kb + tig]);
                bh[nf][1]  = __float_as_uint(Bh[n * ASTRIDE + kb + tig + 4]);
                bl2[nf][0] = __float_as_uint(Bl[n * ASTRIDE + kb + tig]);
                bl2[nf][1] = __float_as_uint(Bl[n * ASTRIDE + kb + tig + 4]);
            }
#pragma unroll
            for (int mf = 0; mf < 2; mf++)
#pragma unroll
                for (int nf = 0; nf < 8; nf++) {
                    mma8(acc[mf][nf], ah[mf], bh[nf]);
                    mma8(acc[mf][nf], ah[mf], bl2[nf]);
                    mma8(acc[mf][nf], al2[mf], bh[nf]);
                }
        }
    };

    const int KT = DD >> 4;  // 16
    load_tile(0, 0);
    CP_COMMIT();
    for (int kt = 0; kt < KT; kt++) {
        if (kt + 1 < KT) {
            load_tile((kt + 1) & 1, kt + 1);
            CP_COMMIT();
            CP_WAIT(1);
        } else {
            CP_WAIT(0);
        }
        __syncthreads();
        compute(kt & 1);
        __syncthreads();
    }

#pragma unroll
    for (int mf = 0; mf < 2; mf++) {
        const int r = i0 + (wm << 5) + (mf << 4) + gid;
#pragma unroll
        for (int nf = 0; nf < 8; nf++) {
            const int col = j0 + (wn << 6) + (nf << 3) + (tig << 1);
            *(float2*)&S[(size_t)r * NN + col]       = make_float2(acc[mf][nf][0], acc[mf][nf][1]);
            *(float2*)&S[(size_t)(r + 8) * NN + col] = make_float2(acc[mf][nf][2], acc[mf][nf][3]);
        }
    }
}

// ---------------------------------------------------------------------------
// av: O[c,n] = sum_m V[c,m] * attn[n,m]  (raw fp32 operands; HW tf32 truncation)
// CTA 128(c) x 256(n), 8 warps (2m x 4n), warp tile 64x64, 3-stage cp.async.
// grid: x = n-tile (9), y = c-tile (16), z = dir*4 + b (8). Dyn smem 90KB.
// ---------------------------------------------------------------------------
__global__ void __launch_bounds__(256) av_mma_kernel(
    const float* __restrict__ L, const float* __restrict__ R,
    const float* __restrict__ attnb, float* __restrict__ out)
{
    extern __shared__ float sm[];
    const int z = blockIdx.z, dir = z >> 2, b = z & 3;
    const float* V  = (dir ? L : R) + (size_t)b * CC * NN;
    const float* At = attnb + (size_t)z * NN * NN;
    float* outb = out + ((size_t)(dir ? BB : 0) + b) * 2 * CC * NN + (size_t)CC * NN;
    const int c0r = blockIdx.y << 7;
    const int n0  = blockIdx.x << 8;

    const int tid = threadIdx.x, wid = tid >> 5, lane = tid & 31;
    const int wm = wid >> 2, wn = wid & 3;
    const int gid = lane >> 2, tig = lane & 3;

    float acc[4][8][4];
#pragma unroll
    for (int i = 0; i < 4; i++)
#pragma unroll
        for (int j = 0; j < 8; j++)
#pragma unroll
            for (int e = 0; e < 4; e++) acc[i][j][e] = 0.f;

    // stage layout: A 2560 floats, B 5120 floats -> 7680 floats/stage, 3 stages
    auto load_tile = [&](int s, int kt) {
        float* As  = sm + s * 7680;
        float* Bs2 = As + 2560;
#pragma unroll
        for (int i = 0; i < 2; i++) {
            int idx = tid + (i << 8);
            int row = idx >> 2, g = idx & 3;
            cp16(smem_u32(&As[row * ASTRIDE + (g << 2)]),
                 V + (size_t)(c0r + row) * NN + (kt << 4) + (g << 2));
        }
#pragma unroll
        for (int i = 0; i < 4; i++) {
            int idx = tid + (i << 8);
            int row = idx >> 2, g = idx & 3;
            cp16(smem_u32(&Bs2[row * ASTRIDE + (g << 2)]),
                 At + (size_t)(n0 + row) * NN + (kt << 4) + (g << 2));
        }
    };

    auto compute = [&](int s) {
        const float* As  = sm + s * 7680;
        const float* Bs2 = As + 2560;
#pragma unroll
        for (int ks = 0; ks < 2; ks++) {
            const int kb = ks << 3;
            uint32_t a[4][4];
#pragma unroll
            for (int mf = 0; mf < 4; mf++) {
                const int r0 = (wm << 6) + (mf << 4) + gid, r1 = r0 + 8;
                a[mf][0] = __float_as_uint(As[r0 * ASTRIDE + kb + tig]);
                a[mf][1] = __float_as_uint(As[r1 * ASTRIDE + kb + tig]);
                a[mf][2] = __float_as_uint(As[r0 * ASTRIDE + kb + tig + 4]);
                a[mf][3] = __float_as_uint(As[r1 * ASTRIDE + kb + tig + 4]);
            }
            uint32_t bf[8][2];
#pragma unroll
            for (int nf = 0; nf < 8; nf++) {
                const int n = (wn << 6) + (nf << 3) + gid;
                bf[nf][0] = __float_as_uint(Bs2[n * ASTRIDE + kb + tig]);
                bf[nf][1] = __float_as_uint(Bs2[n * ASTRIDE + kb + tig + 4]);
            }
#pragma unroll
            for (int mf = 0; mf < 4; mf++)
#pragma unroll
                for (int nf = 0; nf < 8; nf++)
                    mma8(acc[mf][nf], a[mf], bf[nf]);
        }
    };

    const int KT = NN >> 4;  // 144
    load_tile(0, 0); CP_COMMIT();
    load_tile(1, 1); CP_COMMIT();
    for (int kt = 0; kt < KT; kt++) {
        if (kt + 2 < KT) {
            load_tile((kt + 2) % 3, kt + 2);
            CP_COMMIT();
            CP_WAIT(2);
        } else if (kt + 1 < KT) {
            CP_WAIT(1);
        } else {
            CP_WAIT(0);
        }
        __syncthreads();
        compute(kt % 3);
        __syncthreads();
    }

#pragma unroll
    for (int mf = 0; mf < 4; mf++) {
        const int r = c0r + (wm << 6) + (mf << 4) + gid;
#pragma unroll
        for (int nf = 0; nf < 8; nf++) {
            const int col = n0 + (wn << 6) + (nf << 3) + (tig << 1);
            *(float2*)&outb[(size_t)r * NN + col]       = make_float2(acc[mf][nf][0], acc[mf][nf][1]);
            *(float2*)&outb[(size_t)(r + 8) * NN + col] = make_float2(acc[mf][nf][2], acc[mf][nf][3]);
        }
    }
}

// ---------------------------------------------------------------------------
// Row softmax in place over rows of length NN. One block (256 thr) per row.
// ---------------------------------------------------------------------------
__global__ void __launch_bounds__(256) softmax_kernel(float* __restrict__ Sb)
{
    float* S = Sb + (size_t)blockIdx.x * NN;
    const int tid = threadIdx.x;
    __shared__ float red[8];
    __shared__ float bcast;

    float v[9];
    float m = -3.4e38f;
#pragma unroll
    for (int j = 0; j < 9; j++) {
        v[j] = S[tid + (j << 8)];
        m = fmaxf(m, v[j]);
    }
#pragma unroll
    for (int o = 16; o; o >>= 1) m = fmaxf(m, __shfl_xor_sync(0xffffffffu, m, o));
    if ((tid & 31) == 0) red[tid >> 5] = m;
    __syncthreads();
    if (tid == 0) {
        float t = red[0];
#pragma unroll
        for (int i = 1; i < 8; i++) t = fmaxf(t, red[i]);
        bcast = t;
    }
    __syncthreads();
    m = bcast;

    float s = 0.f;
#pragma unroll
    for (int j = 0; j < 9; j++) {
        v[j] = expf(v[j] - m);
        s += v[j];
    }
#pragma unroll
    for (int o = 16; o; o >>= 1) s += __shfl_xor_sync(0xffffffffu, s, o);
    __syncthreads();
    if ((tid & 31) == 0) red[tid >> 5] = s;
    __syncthreads();
    if (tid == 0) {
        float t = 0.f;
#pragma unroll
        for (int i = 0; i < 8; i++) t += red[i];
        bcast = 1.f / t;
    }
    __syncthreads();
    const float inv = bcast;
#pragma unroll
    for (int j = 0; j < 9; j++) S[tid + (j << 8)] = v[j] * inv;
}

// ---------------------------------------------------------------------------
// Copy raw features into the first C channels of each output tensor.
// ---------------------------------------------------------------------------
__global__ void __launch_bounds__(256) copy_kernel(
    const float4* __restrict__ L, const float4* __restrict__ R,
    float4* __restrict__ out)
{
    const size_t total = (size_t)BB * CC * NN / 4;
    size_t i = (size_t)blockIdx.x * 256 + threadIdx.x;
    if (i >= total) return;
    const size_t per_b = (size_t)CC * NN / 4;
    const size_t b = i / per_b;
    const size_t rem = i - b * per_b;
    const size_t dst = b * ((size_t)2 * CC * NN / 4) + rem;
    out[dst] = L[i];
    out[dst + (size_t)BB * 2 * CC * NN / 4] = R[i];
}

// ---------------------------------------------------------------------------
extern "C" void kernel_launch(void* const* d_in, const int* in_sizes, int n_in,
                              void* d_out, int out_size)
{
    const float* L  = (const float*)d_in[0];
    const float* R  = (const float*)d_in[1];
    const float* wq = (const float*)d_in[2];
    const float* bq = (const float*)d_in[3];
    const float* wr = (const float*)d_in[4];
    const float* br = (const float*)d_in[5];
    float* out = (float*)d_out;

    float *qh, *ql, *kh, *kl, *attn;
    cudaGetSymbolAddress((void**)&qh, g_qh);
    cudaGetSymbolAddress((void**)&ql, g_ql);
    cudaGetSymbolAddress((void**)&kh, g_kh);
    cudaGetSymbolAddress((void**)&kl, g_kl);
    cudaGetSymbolAddress((void**)&attn, g_attn);

    cudaFuncSetAttribute(scores_mma_kernel, cudaFuncAttributeMaxDynamicSharedMemorySize, 81920);
    cudaFuncSetAttribute(av_mma_kernel, cudaFuncAttributeMaxDynamicSharedMemorySize, 92160);

    proj_mma_kernel<<<dim3(DD / 128, NN / 128, 16), 256>>>(L, R, wq, bq, wr, br, qh, ql, kh, kl);
    scores_mma_kernel<<<dim3(NN / 128, NN / 128, 8), 256, 81920>>>(qh, ql, kh, kl, attn);
    softmax_kernel<<<2 * BB * NN, 256>>>(attn);
    av_mma_kernel<<<dim3(NN / 256, CC / 128, 8), 256, 92160>>>(L, R, attn, out);

    const size_t ncpy = (size_t)BB * CC * NN / 4;
    copy_kernel<<<(unsigned)((ncpy + 255) / 256), 256>>>(
        (const float4*)L, (const float4*)R, (float4*)out);
}

// round 5
// speedup vs baseline: 3.0299x; 1.1998x over previous
#include <cuda_runtime.h>
#include <cstdint>

#define BB 4
#define CC 2048
#define NN 2304   // 48*48
#define DD 256

// ---------------------------------------------------------------------------
// Scratch (__device__ globals; no cudaMalloc allowed)
// q,k stored split (hi/lo tf32 components) [dir][b][n][d]
// ---------------------------------------------------------------------------
__device__ float g_qh[2ull * BB * NN * DD];
__device__ float g_ql[2ull * BB * NN * DD];
__device__ float g_kh[2ull * BB * NN * DD];
__device__ float g_kl[2ull * BB * NN * DD];
__device__ float g_attn[2ull * BB * NN * NN];

// ---------------------------------------------------------------------------
// helpers
// ---------------------------------------------------------------------------
__device__ __forceinline__ uint32_t smem_u32(const void* p) {
    uint32_t a;
    asm("{ .reg .u64 t; cvta.to.shared.u64 t, %1; cvt.u32.u64 %0, t; }" : "=r"(a) : "l"(p));
    return a;
}

__device__ __forceinline__ void cp16(uint32_t dst, const void* src) {
    asm volatile("cp.async.cg.shared.global [%0], [%1], 16;" :: "r"(dst), "l"(src));
}
#define CP_COMMIT() asm volatile("cp.async.commit_group;")
#define CP_WAIT(n)  asm volatile("cp.async.wait_group %0;" :: "n"(n))

__device__ __forceinline__ uint32_t f2tf32(float x) {
    uint32_t u;
    asm("cvt.rna.tf32.f32 %0, %1;" : "=r"(u) : "f"(x));
    return u;
}

__device__ __forceinline__ void mma8(float* c, const uint32_t* a, const uint32_t* b) {
    asm volatile(
        "mma.sync.aligned.m16n8k8.row.col.f32.tf32.tf32.f32 "
        "{%0,%1,%2,%3}, {%4,%5,%6,%7}, {%8,%9}, {%0,%1,%2,%3};"
        : "+f"(c[0]), "+f"(c[1]), "+f"(c[2]), "+f"(c[3])
        : "r"(a[0]), "r"(a[1]), "r"(a[2]), "r"(a[3]), "r"(b[0]), "r"(b[1]));
}

#define ST16 20   // smem row stride for 16-col k-tiles
#define ST32 36   // smem row stride for 32-col k-tiles

// ===========================================================================
// proj: q'[n,d] = sum_c X[c,n] * W[d,c] + bias[d]   (tf32x3, on-the-fly cvt)
// CTA 128(n) x 128(d), 8 warps (4m x 2n), warp 32x64, KT=32, 3-stage, 1 sync.
// Epilogue splits result into hi/lo tf32 for the scores kernel.
// grid: x = d-tile (2), y = n-tile (18), z = pidx*4 + b (16)
// ===========================================================================
#define PROJ_STAGE 9216   // floats per stage: A 128*36 + B 128*36

__global__ void __launch_bounds__(256) proj_mma_kernel(
    const float* __restrict__ L, const float* __restrict__ R,
    const float* __restrict__ wq, const float* __restrict__ bq,
    const float* __restrict__ wr, const float* __restrict__ br,
    float* __restrict__ qh_g, float* __restrict__ ql_g,
    float* __restrict__ kh_g, float* __restrict__ kl_g)
{
    extern __shared__ float sm[];

    const int z = blockIdx.z, pidx = z >> 2, b = z & 3;
    const float* X = ((pidx == 0) || (pidx == 3)) ? L : R;
    X += (size_t)b * CC * NN;
    const float* W    = (pidx & 1) ? wr : wq;
    const float* bias = (pidx & 1) ? br : bq;
    float* oh = ((pidx & 1) ? kh_g : qh_g) + ((size_t)(pidx >> 1) * BB + b) * NN * DD;
    float* ol = ((pidx & 1) ? kl_g : ql_g) + ((size_t)(pidx >> 1) * BB + b) * NN * DD;

    const int m0 = blockIdx.y << 7;   // over n
    const int n0 = blockIdx.x << 7;   // over d

    const int tid = threadIdx.x, wid = tid >> 5, lane = tid & 31;
    const int wm = wid >> 1, wn = wid & 1;
    const int gid = lane >> 2, tig = lane & 3;

    float acc[2][8][4];
#pragma unroll
    for (int i = 0; i < 2; i++)
#pragma unroll
        for (int j = 0; j < 8; j++)
#pragma unroll
            for (int e = 0; e < 4; e++) acc[i][j][e] = 0.f;

    auto load_tile = [&](int s, int kt) {
        float* As  = sm + s * PROJ_STAGE;
        float* Bs2 = As + 128 * ST32;
        // B = W rows (d), k contiguous: 128 rows x 8 groups
#pragma unroll
        for (int i = 0; i < 4; i++) {
            int idx = tid + (i << 8);
            int row = idx >> 3, g = idx & 7;
            cp16(smem_u32(&Bs2[row * ST32 + (g << 2)]),
                 W + (size_t)(n0 + row) * CC + (kt << 5) + (g << 2));
        }
        // A = X transpose: X[c][n] -> As[n][c], 128 n x 32 c
        const int n = tid & 127, cg = tid >> 7;
#pragma unroll
        for (int i = 0; i < 4; i++) {
            int c0 = (cg + 2 * i) << 2;
            const float* s2 = X + (size_t)((kt << 5) + c0) * NN + m0 + n;
            float4 v;
            v.x = s2[0]; v.y = s2[NN]; v.z = s2[2 * NN]; v.w = s2[3 * NN];
            *(float4*)&As[n * ST32 + c0] = v;
        }
    };

    auto compute = [&](int s) {
        const float* As  = sm + s * PROJ_STAGE;
        const float* Bs2 = As + 128 * ST32;
#pragma unroll
        for (int ks = 0; ks < 4; ks++) {
            const int kb = ks << 3;
            uint32_t ah[2][4], al[2][4];
#pragma unroll
            for (int mf = 0; mf < 2; mf++) {
                const int r0 = (wm << 5) + (mf << 4) + gid, r1 = r0 + 8;
                float raw[4];
                raw[0] = As[r0 * ST32 + kb + tig];
                raw[1] = As[r1 * ST32 + kb + tig];
                raw[2] = As[r0 * ST32 + kb + tig + 4];
                raw[3] = As[r1 * ST32 + kb + tig + 4];
#pragma unroll
                for (int e = 0; e < 4; e++) {
                    ah[mf][e] = f2tf32(raw[e]);
                    al[mf][e] = f2tf32(raw[e] - __uint_as_float(ah[mf][e]));
                }
            }
            uint32_t bh[8][2], bl[8][2];
#pragma unroll
            for (int nf = 0; nf < 8; nf++) {
                const int n = (wn << 6) + (nf << 3) + gid;
                float r0 = Bs2[n * ST32 + kb + tig];
                float r1 = Bs2[n * ST32 + kb + tig + 4];
                bh[nf][0] = f2tf32(r0);
                bh[nf][1] = f2tf32(r1);
                bl[nf][0] = f2tf32(r0 - __uint_as_float(bh[nf][0]));
                bl[nf][1] = f2tf32(r1 - __uint_as_float(bh[nf][1]));
            }
#pragma unroll
            for (int mf = 0; mf < 2; mf++)
#pragma unroll
                for (int nf = 0; nf < 8; nf++) {
                    mma8(acc[mf][nf], ah[mf], bh[nf]);
                    mma8(acc[mf][nf], ah[mf], bl[nf]);
                    mma8(acc[mf][nf], al[mf], bh[nf]);
                }
        }
    };

    const int KT = CC >> 5;  // 64
    load_tile(0, 0); CP_COMMIT();
    load_tile(1, 1); CP_COMMIT();
    for (int kt = 0; kt < KT; kt++) {
        CP_WAIT(1);
        __syncthreads();
        compute(kt % 3);
        if (kt + 2 < KT) load_tile((kt + 2) % 3, kt + 2);
        CP_COMMIT();
    }

    // epilogue: add bias, split into hi/lo tf32
#pragma unroll
    for (int mf = 0; mf < 2; mf++) {
        const int r = m0 + (wm << 5) + (mf << 4) + gid;
#pragma unroll
        for (int nf = 0; nf < 8; nf++) {
            const int col = n0 + (wn << 6) + (nf << 3) + (tig << 1);
            const float b0 = bias[col], b1 = bias[col + 1];
            float v[4] = { acc[mf][nf][0] + b0, acc[mf][nf][1] + b1,
                           acc[mf][nf][2] + b0, acc[mf][nf][3] + b1 };
            float hi[4], lo[4];
#pragma unroll
            for (int e = 0; e < 4; e++) {
                hi[e] = __uint_as_float(f2tf32(v[e]));
                lo[e] = __uint_as_float(f2tf32(v[e] - hi[e]));
            }
            *(float2*)&oh[(size_t)r * DD + col]       = make_float2(hi[0], hi[1]);
            *(float2*)&oh[(size_t)(r + 8) * DD + col] = make_float2(hi[2], hi[3]);
            *(float2*)&ol[(size_t)r * DD + col]       = make_float2(lo[0], lo[1]);
            *(float2*)&ol[(size_t)(r + 8) * DD + col] = make_float2(lo[2], lo[3]);
        }
    }
}

// ===========================================================================
// scores: S = qh.kh + qh.kl + ql.kh  (pure-MMA mainloop, pre-split operands)
// CTA 128x128, 8 warps (4m x 2n), warp 32x64, KT=16, 3-stage, 1 sync,
// register fragment double-buffering.
// grid: x = j-tile (18), y = i-tile (18), z = dir*4 + b (8)
// ===========================================================================
#define SC_STAGE 10240   // 4 arrays x 128*20 floats

__global__ void __launch_bounds__(256) scores_mma_kernel(
    const float* __restrict__ qh_g, const float* __restrict__ ql_g,
    const float* __restrict__ kh_g, const float* __restrict__ kl_g,
    float* __restrict__ Sb)
{
    extern __shared__ float sm[];
    const size_t z = blockIdx.z;
    const float* qh = qh_g + z * NN * DD;
    const float* ql = ql_g + z * NN * DD;
    const float* kh = kh_g + z * NN * DD;
    const float* kl = kl_g + z * NN * DD;
    float* S = Sb + z * NN * NN;
    const int i0 = blockIdx.y << 7;
    const int j0 = blockIdx.x << 7;

    const int tid = threadIdx.x, wid = tid >> 5, lane = tid & 31;
    const int wm = wid >> 1, wn = wid & 1;
    const int gid = lane >> 2, tig = lane & 3;

    float acc[2][8][4];
#pragma unroll
    for (int i = 0; i < 2; i++)
#pragma unroll
        for (int j = 0; j < 8; j++)
#pragma unroll
            for (int e = 0; e < 4; e++) acc[i][j][e] = 0.f;

    auto load_tile = [&](int s, int kt) {
        float* p = sm + s * SC_STAGE;
        const float* srcs[4] = { qh + (size_t)i0 * DD, ql + (size_t)i0 * DD,
                                 kh + (size_t)j0 * DD, kl + (size_t)j0 * DD };
#pragma unroll
        for (int a = 0; a < 4; a++) {
#pragma unroll
            for (int i = 0; i < 2; i++) {
                int idx = tid + (i << 8);
                int row = idx >> 2, g = idx & 3;
                cp16(smem_u32(&p[a * 2560 + row * ST16 + (g << 2)]),
                     srcs[a] + (size_t)row * DD + (kt << 4) + (g << 2));
            }
        }
    };

    auto ldfrag = [&](const float* Ah, const float* Al, const float* Bh, const float* Bl,
                      int ks, uint32_t ah[2][4], uint32_t al2[2][4],
                      uint32_t bh[8][2], uint32_t bl2[8][2]) {
        const int kb = ks << 3;
#pragma unroll
        for (int mf = 0; mf < 2; mf++) {
            const int r0 = (wm << 5) + (mf << 4) + gid, r1 = r0 + 8;
            ah[mf][0]  = __float_as_uint(Ah[r0 * ST16 + kb + tig]);
            ah[mf][1]  = __float_as_uint(Ah[r1 * ST16 + kb + tig]);
            ah[mf][2]  = __float_as_uint(Ah[r0 * ST16 + kb + tig + 4]);
            ah[mf][3]  = __float_as_uint(Ah[r1 * ST16 + kb + tig + 4]);
            al2[mf][0] = __float_as_uint(Al[r0 * ST16 + kb + tig]);
            al2[mf][1] = __float_as_uint(Al[r1 * ST16 + kb + tig]);
            al2[mf][2] = __float_as_uint(Al[r0 * ST16 + kb + tig + 4]);
            al2[mf][3] = __float_as_uint(Al[r1 * ST16 + kb + tig + 4]);
        }
#pragma unroll
        for (int nf = 0; nf < 8; nf++) {
            const int n = (wn << 6) + (nf << 3) + gid;
            bh[nf][0]  = __float_as_uint(Bh[n * ST16 + kb + tig]);
            bh[nf][1]  = __float_as_uint(Bh[n * ST16 + kb + tig + 4]);
            bl2[nf][0] = __float_as_uint(Bl[n * ST16 + kb + tig]);
            bl2[nf][1] = __float_as_uint(Bl[n * ST16 + kb + tig + 4]);
        }
    };

    auto compute = [&](int s) {
        const float* Ah = sm + s * SC_STAGE;
        const float* Al = Ah + 2560;
        const float* Bh = Ah + 5120;
        const float* Bl = Ah + 7680;
        uint32_t ah[2][2][4], al2[2][2][4], bh[2][8][2], bl2[2][8][2];
        ldfrag(Ah, Al, Bh, Bl, 0, ah[0], al2[0], bh[0], bl2[0]);
#pragma unroll
        for (int ks = 0; ks < 2; ks++) {
            const int cur = ks & 1, nxt = cur ^ 1;
            if (ks < 1) ldfrag(Ah, Al, Bh, Bl, ks + 1, ah[nxt], al2[nxt], bh[nxt], bl2[nxt]);
#pragma unroll
            for (int mf = 0; mf < 2; mf++)
#pragma unroll
                for (int nf = 0; nf < 8; nf++) {
                    mma8(acc[mf][nf], ah[cur][mf], bh[cur][nf]);
                    mma8(acc[mf][nf], ah[cur][mf], bl2[cur][nf]);
                    mma8(acc[mf][nf], al2[cur][mf], bh[cur][nf]);
                }
        }
    };

    const int KT = DD >> 4;  // 16
    load_tile(0, 0); CP_COMMIT();
    load_tile(1, 1); CP_COMMIT();
    for (int kt = 0; kt < KT; kt++) {
        CP_WAIT(1);
        __syncthreads();
        compute(kt % 3);
        if (kt + 2 < KT) load_tile((kt + 2) % 3, kt + 2);
        CP_COMMIT();
    }

#pragma unroll
    for (int mf = 0; mf < 2; mf++) {
        const int r = i0 + (wm << 5) + (mf << 4) + gid;
#pragma unroll
        for (int nf = 0; nf < 8; nf++) {
            const int col = j0 + (wn << 6) + (nf << 3) + (tig << 1);
            *(float2*)&S[(size_t)r * NN + col]       = make_float2(acc[mf][nf][0], acc[mf][nf][1]);
            *(float2*)&S[(size_t)(r + 8) * NN + col] = make_float2(acc[mf][nf][2], acc[mf][nf][3]);
        }
    }
}

// ===========================================================================
// av: O[c,n] = sum_m V[c,m] * attn[n,m]  (raw fp32 operands, HW tf32 trunc)
// CTA 128(c) x 256(n), 8 warps (2m x 4n), warp 64x64, KT=32, 3-stage, 1 sync,
// register fragment double-buffering.
// grid: x = n-tile (9), y = c-tile (16), z = dir*4 + b (8)
// ===========================================================================
#define AV_STAGE 13824   // A 128*36 + B 256*36 floats

__global__ void __launch_bounds__(256) av_mma_kernel(
    const float* __restrict__ L, const float* __restrict__ R,
    const float* __restrict__ attnb, float* __restrict__ out)
{
    extern __shared__ float sm[];
    const int z = blockIdx.z, dir = z >> 2, b = z & 3;
    const float* V  = (dir ? L : R) + (size_t)b * CC * NN;
    const float* At = attnb + (size_t)z * NN * NN;
    float* outb = out + ((size_t)(dir ? BB : 0) + b) * 2 * CC * NN + (size_t)CC * NN;
    const int c0r = blockIdx.y << 7;
    const int n0  = blockIdx.x << 8;

    const int tid = threadIdx.x, wid = tid >> 5, lane = tid & 31;
    const int wm = wid >> 2, wn = wid & 3;
    const int gid = lane >> 2, tig = lane & 3;

    float acc[4][8][4];
#pragma unroll
    for (int i = 0; i < 4; i++)
#pragma unroll
        for (int j = 0; j < 8; j++)
#pragma unroll
            for (int e = 0; e < 4; e++) acc[i][j][e] = 0.f;

    auto load_tile = [&](int s, int kt) {
        float* As  = sm + s * AV_STAGE;
        float* Bs2 = As + 128 * ST32;
        // A: 128 rows x 8 groups of 4
#pragma unroll
        for (int i = 0; i < 4; i++) {
            int idx = tid + (i << 8);
            int row = idx >> 3, g = idx & 7;
            cp16(smem_u32(&As[row * ST32 + (g << 2)]),
                 V + (size_t)(c0r + row) * NN + (kt << 5) + (g << 2));
        }
        // B: 256 rows x 8 groups of 4
#pragma unroll
        for (int i = 0; i < 8; i++) {
            int idx = tid + (i << 8);
            int row = idx >> 3, g = idx & 7;
            cp16(smem_u32(&Bs2[row * ST32 + (g << 2)]),
                 At + (size_t)(n0 + row) * NN + (kt << 5) + (g << 2));
        }
    };

    auto ldfrag = [&](const float* As, const float* Bs2, int ks,
                      uint32_t a[4][4], uint32_t bf[8][2]) {
        const int kb = ks << 3;
#pragma unroll
        for (int mf = 0; mf < 4; mf++) {
            const int r0 = (wm << 6) + (mf << 4) + gid, r1 = r0 + 8;
            a[mf][0] = __float_as_uint(As[r0 * ST32 + kb + tig]);
            a[mf][1] = __float_as_uint(As[r1 * ST32 + kb + tig]);
            a[mf][2] = __float_as_uint(As[r0 * ST32 + kb + tig + 4]);
            a[mf][3] = __float_as_uint(As[r1 * ST32 + kb + tig + 4]);
        }
#pragma unroll
        for (int nf = 0; nf < 8; nf++) {
            const int n = (wn << 6) + (nf << 3) + gid;
            bf[nf][0] = __float_as_uint(Bs2[n * ST32 + kb + tig]);
            bf[nf][1] = __float_as_uint(Bs2[n * ST32 + kb + tig + 4]);
        }
    };

    auto compute = [&](int s) {
        const float* As  = sm + s * AV_STAGE;
        const float* Bs2 = As + 128 * ST32;
        uint32_t a[2][4][4], bf[2][8][2];
        ldfrag(As, Bs2, 0, a[0], bf[0]);
#pragma unroll
        for (int ks = 0; ks < 4; ks++) {
            const int cur = ks & 1, nxt = cur ^ 1;
            if (ks < 3) ldfrag(As, Bs2, ks + 1, a[nxt], bf[nxt]);
#pragma unroll
            for (int mf = 0; mf < 4; mf++)
#pragma unroll
                for (int nf = 0; nf < 8; nf++)
                    mma8(acc[mf][nf], a[cur][mf], bf[cur][nf]);
        }
    };

    const int KT = NN >> 5;  // 72
    load_tile(0, 0); CP_COMMIT();
    load_tile(1, 1); CP_COMMIT();
    for (int kt = 0; kt < KT; kt++) {
        CP_WAIT(1);
        __syncthreads();
        compute(kt % 3);
        if (kt + 2 < KT) load_tile((kt + 2) % 3, kt + 2);
        CP_COMMIT();
    }

#pragma unroll
    for (int mf = 0; mf < 4; mf++) {
        const int r = c0r + (wm << 6) + (mf << 4) + gid;
#pragma unroll
        for (int nf = 0; nf < 8; nf++) {
            const int col = n0 + (wn << 6) + (nf << 3) + (tig << 1);
            *(float2*)&outb[(size_t)r * NN + col]       = make_float2(acc[mf][nf][0], acc[mf][nf][1]);
            *(float2*)&outb[(size_t)(r + 8) * NN + col] = make_float2(acc[mf][nf][2], acc[mf][nf][3]);
        }
    }
}

// ---------------------------------------------------------------------------
// Row softmax in place over rows of length NN. One block (256 thr) per row.
// ---------------------------------------------------------------------------
__global__ void __launch_bounds__(256) softmax_kernel(float* __restrict__ Sb)
{
    float* S = Sb + (size_t)blockIdx.x * NN;
    const int tid = threadIdx.x;
    __shared__ float red[8];
    __shared__ float bcast;

    float v[9];
    float m = -3.4e38f;
#pragma unroll
    for (int j = 0; j < 9; j++) {
        v[j] = S[tid + (j << 8)];
        m = fmaxf(m, v[j]);
    }
#pragma unroll
    for (int o = 16; o; o >>= 1) m = fmaxf(m, __shfl_xor_sync(0xffffffffu, m, o));
    if ((tid & 31) == 0) red[tid >> 5] = m;
    __syncthreads();
    if (tid == 0) {
        float t = red[0];
#pragma unroll
        for (int i = 1; i < 8; i++) t = fmaxf(t, red[i]);
        bcast = t;
    }
    __syncthreads();
    m = bcast;

    float s = 0.f;
#pragma unroll
    for (int j = 0; j < 9; j++) {
        v[j] = expf(v[j] - m);
        s += v[j];
    }
#pragma unroll
    for (int o = 16; o; o >>= 1) s += __shfl_xor_sync(0xffffffffu, s, o);
    __syncthreads();
    if ((tid & 31) == 0) red[tid >> 5] = s;
    __syncthreads();
    if (tid == 0) {
        float t = 0.f;
#pragma unroll
        for (int i = 0; i < 8; i++) t += red[i];
        bcast = 1.f / t;
    }
    __syncthreads();
    const float inv = bcast;
#pragma unroll
    for (int j = 0; j < 9; j++) S[tid + (j << 8)] = v[j] * inv;
}

// ---------------------------------------------------------------------------
// Copy raw features into the first C channels of each output tensor.
// ---------------------------------------------------------------------------
__global__ void __launch_bounds__(256) copy_kernel(
    const float4* __restrict__ L, const float4* __restrict__ R,
    float4* __restrict__ out)
{
    const size_t total = (size_t)BB * CC * NN / 4;
    size_t i = (size_t)blockIdx.x * 256 + threadIdx.x;
    if (i >= total) return;
    const size_t per_b = (size_t)CC * NN / 4;
    const size_t b = i / per_b;
    const size_t rem = i - b * per_b;
    const size_t dst = b * ((size_t)2 * CC * NN / 4) + rem;
    out[dst] = L[i];
    out[dst + (size_t)BB * 2 * CC * NN / 4] = R[i];
}

// ---------------------------------------------------------------------------
extern "C" void kernel_launch(void* const* d_in, const int* in_sizes, int n_in,
                              void* d_out, int out_size)
{
    const float* L  = (const float*)d_in[0];
    const float* R  = (const float*)d_in[1];
    const float* wq = (const float*)d_in[2];
    const float* bq = (const float*)d_in[3];
    const float* wr = (const float*)d_in[4];
    const float* br = (const float*)d_in[5];
    float* out = (float*)d_out;

    float *qh, *ql, *kh, *kl, *attn;
    cudaGetSymbolAddress((void**)&qh, g_qh);
    cudaGetSymbolAddress((void**)&ql, g_ql);
    cudaGetSymbolAddress((void**)&kh, g_kh);
    cudaGetSymbolAddress((void**)&kl, g_kl);
    cudaGetSymbolAddress((void**)&attn, g_attn);

    cudaFuncSetAttribute(proj_mma_kernel, cudaFuncAttributeMaxDynamicSharedMemorySize, 3 * PROJ_STAGE * 4);
    cudaFuncSetAttribute(scores_mma_kernel, cudaFuncAttributeMaxDynamicSharedMemorySize, 3 * SC_STAGE * 4);
    cudaFuncSetAttribute(av_mma_kernel, cudaFuncAttributeMaxDynamicSharedMemorySize, 3 * AV_STAGE * 4);

    proj_mma_kernel<<<dim3(DD / 128, NN / 128, 16), 256, 3 * PROJ_STAGE * 4>>>(
        L, R, wq, bq, wr, br, qh, ql, kh, kl);
    scores_mma_kernel<<<dim3(NN / 128, NN / 128, 8), 256, 3 * SC_STAGE * 4>>>(qh, ql, kh, kl, attn);
    softmax_kernel<<<2 * BB * NN, 256>>>(attn);
    av_mma_kernel<<<dim3(NN / 256, CC / 128, 8), 256, 3 * AV_STAGE * 4>>>(L, R, attn, out);

    const size_t ncpy = (size_t)BB * CC * NN / 4;
    copy_kernel<<<(unsigned)((ncpy + 255) / 256), 256>>>(
        (const float4*)L, (const float4*)R, (float4*)out);
}

// round 6
// speedup vs baseline: 3.8709x; 1.2776x over previous
#include <cuda_runtime.h>
#include <cuda_bf16.h>
#include <cstdint>

#define BB 4
#define CC 2048
#define NN 2304   // 48*48
#define DD 256

typedef __nv_bfloat16 bf16;
typedef __nv_bfloat162 bf162;

// ---------------------------------------------------------------------------
// Scratch (__device__ globals)
// ---------------------------------------------------------------------------
__device__ bf16 g_xh[2ull * BB * NN * CC];   // X transposed [src*4+b][n][c], hi
__device__ bf16 g_xl[2ull * BB * NN * CC];   // lo
__device__ bf16 g_wh[2ull * DD * CC];        // [wq;wr][d][c] hi
__device__ bf16 g_wl[2ull * DD * CC];
__device__ bf16 g_qh[2ull * BB * NN * DD];   // [dir*4+b][n][d]
__device__ bf16 g_ql[2ull * BB * NN * DD];
__device__ bf16 g_kh[2ull * BB * NN * DD];
__device__ bf16 g_kl[2ull * BB * NN * DD];
__device__ float g_attn[2ull * BB * NN * NN];

// ---------------------------------------------------------------------------
// helpers
// ---------------------------------------------------------------------------
__device__ __forceinline__ uint32_t smem_u32(const void* p) {
    uint32_t a;
    asm("{ .reg .u64 t; cvta.to.shared.u64 t, %1; cvt.u32.u64 %0, t; }" : "=r"(a) : "l"(p));
    return a;
}

__device__ __forceinline__ void cp16(uint32_t dst, const void* src) {
    asm volatile("cp.async.cg.shared.global [%0], [%1], 16;" :: "r"(dst), "l"(src));
}
#define CP_COMMIT() asm volatile("cp.async.commit_group;")
#define CP_WAIT(n)  asm volatile("cp.async.wait_group %0;" :: "n"(n))

__device__ __forceinline__ void mma8(float* c, const uint32_t* a, const uint32_t* b) {
    asm volatile(
        "mma.sync.aligned.m16n8k8.row.col.f32.tf32.tf32.f32 "
        "{%0,%1,%2,%3}, {%4,%5,%6,%7}, {%8,%9}, {%0,%1,%2,%3};"
        : "+f"(c[0]), "+f"(c[1]), "+f"(c[2]), "+f"(c[3])
        : "r"(a[0]), "r"(a[1]), "r"(a[2]), "r"(a[3]), "r"(b[0]), "r"(b[1]));
}

__device__ __forceinline__ void mma16(float* c, const uint32_t* a, const uint32_t* b) {
    asm volatile(
        "mma.sync.aligned.m16n8k16.row.col.f32.bf16.bf16.f32 "
        "{%0,%1,%2,%3}, {%4,%5,%6,%7}, {%8,%9}, {%0,%1,%2,%3};"
        : "+f"(c[0]), "+f"(c[1]), "+f"(c[2]), "+f"(c[3])
        : "r"(a[0]), "r"(a[1]), "r"(a[2]), "r"(a[3]), "r"(b[0]), "r"(b[1]));
}

__device__ __forceinline__ void split_bf(float v, bf16& h, bf16& l) {
    h = __float2bfloat16(v);
    l = __float2bfloat16(v - __bfloat162float(h));
}

// fast exp: exp2 poly (Taylor deg-6, rel err ~1.5e-5), no MUFU
__device__ __forceinline__ float fexp(float x) {
    float t = fmaxf(x * 1.44269504089f, -120.f);
    float fi = floorf(t);
    float f = t - fi;
    float p = 1.54953e-4f;
    p = fmaf(p, f, 0.00133335581f);
    p = fmaf(p, f, 0.00961812911f);
    p = fmaf(p, f, 0.0555041087f);
    p = fmaf(p, f, 0.240226507f);
    p = fmaf(p, f, 0.693147181f);
    p = fmaf(p, f, 1.0f);
    return __int_as_float(__float_as_int(p) + ((int)fi << 23));
}

// ===========================================================================
// split_w: W [d][c] fp32 -> hi/lo bf16 (wq then wr concatenated)
// ===========================================================================
__global__ void __launch_bounds__(256) split_w_kernel(
    const float* __restrict__ wq, const float* __restrict__ wr,
    bf16* __restrict__ wh, bf16* __restrict__ wl)
{
    const size_t total2 = (size_t)2 * DD * CC / 2;   // u32 outputs
    size_t i = (size_t)blockIdx.x * 256 + threadIdx.x;
    if (i >= total2) return;
    size_t p = i * 2;
    const float* src = (p < (size_t)DD * CC) ? wq + p : wr + (p - (size_t)DD * CC);
    float2 v = *(const float2*)src;
    bf16 h0, l0, h1, l1;
    split_bf(v.x, h0, l0);
    split_bf(v.y, h1, l1);
    *(bf162*)&wh[p] = bf162(h0, h1);
    *(bf162*)&wl[p] = bf162(l0, l1);
}

// ===========================================================================
// split_x: X [src][b][c][n] fp32 -> Xt [src*4+b][n][c] hi/lo bf16 (transpose)
// 64x64 tiles via smem. grid (36, 32, 8)
// ===========================================================================
__global__ void __launch_bounds__(256) split_x_kernel(
    const float* __restrict__ L, const float* __restrict__ R,
    bf16* __restrict__ xh, bf16* __restrict__ xl)
{
    __shared__ float t[64][67];
    const int z = blockIdx.z, src = z >> 2, b = z & 3;
    const float* X = (src ? R : L) + (size_t)b * CC * NN;
    bf16* oh = xh + (size_t)z * NN * CC;
    bf16* ol = xl + (size_t)z * NN * CC;
    const int n0 = blockIdx.x << 6, c0 = blockIdx.y << 6;
    const int tid = threadIdx.x;

#pragma unroll
    for (int i = 0; i < 16; i++) {
        int idx = tid + (i << 8);
        int cc = idx >> 6, n = idx & 63;
        t[cc][n] = X[(size_t)(c0 + cc) * NN + n0 + n];
    }
    __syncthreads();
#pragma unroll
    for (int i = 0; i < 8; i++) {
        int idx = tid + (i << 8);
        int n = idx >> 5, cu = idx & 31;
        float v0 = t[2 * cu][n], v1 = t[2 * cu + 1][n];
        bf16 h0, l0, h1, l1;
        split_bf(v0, h0, l0);
        split_bf(v1, h1, l1);
        size_t off = (size_t)(n0 + n) * CC + c0 + 2 * cu;
        *(bf162*)&oh[off] = bf162(h0, h1);
        *(bf162*)&ol[off] = bf162(l0, l1);
    }
}

// ===========================================================================
// proj: q'[n,d] = sum_c Xt[n,c] * W[d,c] + bias[d]  -- bf16x3 pure-MMA
// CTA 128(n) x 256(d=full), 8 warps 2m x 4n, warp 64x64, k-tile 32, 3-stage.
// Epilogue: add bias, split to bf16 hi/lo q/k buffers.
// grid: x = which W (0=wq->q, 1=wr->k), y = n-tile (18), z = src*4+b (8)
// ===========================================================================
#define PST 40                 // bf16 units per smem row (32 + 8 pad)
#define PROJ_STAGE_U 30720     // (128+128+256+256) rows * 40 units

__global__ void __launch_bounds__(256) proj_bf16_kernel(
    const bf16* __restrict__ xh, const bf16* __restrict__ xl,
    const bf16* __restrict__ whg, const bf16* __restrict__ wlg,
    const float* __restrict__ bq, const float* __restrict__ br,
    bf16* __restrict__ qh_g, bf16* __restrict__ ql_g,
    bf16* __restrict__ kh_g, bf16* __restrict__ kl_g)
{
    extern __shared__ bf16 smb[];
    const int x = blockIdx.x;
    const int z = blockIdx.z, src = z >> 2, b = z & 3;
    const bf16* Xh = xh + (size_t)z * NN * CC;
    const bf16* Xl = xl + (size_t)z * NN * CC;
    const bf16* Wh = whg + (size_t)x * DD * CC;
    const bf16* Wl = wlg + (size_t)x * DD * CC;
    const float* bias = x ? br : bq;
    const int dir = x ? (src ^ 1) : src;
    bf16* oh = (x ? kh_g : qh_g) + ((size_t)dir * BB + b) * NN * DD;
    bf16* ol = (x ? kl_g : ql_g) + ((size_t)dir * BB + b) * NN * DD;
    const int m0 = blockIdx.y << 7;

    const int tid = threadIdx.x, wid = tid >> 5, lane = tid & 31;
    const int wm = wid >> 2, wn = wid & 3;
    const int gid = lane >> 2, tig = lane & 3;

    float acc[4][8][4];
#pragma unroll
    for (int i = 0; i < 4; i++)
#pragma unroll
        for (int j = 0; j < 8; j++)
#pragma unroll
            for (int e = 0; e < 4; e++) acc[i][j][e] = 0.f;

    auto load_tile = [&](int s, int kt) {
        bf16* st = smb + (size_t)s * PROJ_STAGE_U;
        const int kb = kt << 5;
#pragma unroll
        for (int i = 0; i < 12; i++) {
            int idx = tid + (i << 8);
            int row = idx >> 2, ch = idx & 3;
            const bf16* sp;
            uint32_t dst;
            if (row < 128) {
                sp = Xh + (size_t)(m0 + row) * CC + kb + ch * 8;
                dst = smem_u32(st + row * PST + ch * 8);
            } else if (row < 256) {
                sp = Xl + (size_t)(m0 + row - 128) * CC + kb + ch * 8;
                dst = smem_u32(st + 5120 + (row - 128) * PST + ch * 8);
            } else if (row < 512) {
                sp = Wh + (size_t)(row - 256) * CC + kb + ch * 8;
                dst = smem_u32(st + 10240 + (row - 256) * PST + ch * 8);
            } else {
                sp = Wl + (size_t)(row - 512) * CC + kb + ch * 8;
                dst = smem_u32(st + 20480 + (row - 512) * PST + ch * 8);
            }
            cp16(dst, sp);
        }
    };

    auto compute = [&](int s) {
        const bf16* st = smb + (size_t)s * PROJ_STAGE_U;
        const bf16* Ah = st;
        const bf16* Al = st + 5120;
        const bf16* Bh = st + 10240;
        const bf16* Bl = st + 20480;
#pragma unroll
        for (int ks = 0; ks < 2; ks++) {
            const int ko = ks << 4;
            uint32_t ah[4][4], al[4][4];
#pragma unroll
            for (int mf = 0; mf < 4; mf++) {
                const int r0 = (wm << 6) + (mf << 4) + gid, r1 = r0 + 8;
                ah[mf][0] = *(const uint32_t*)(Ah + r0 * PST + ko + 2 * tig);
                ah[mf][1] = *(const uint32_t*)(Ah + r1 * PST + ko + 2 * tig);
                ah[mf][2] = *(const uint32_t*)(Ah + r0 * PST + ko + 8 + 2 * tig);
                ah[mf][3] = *(const uint32_t*)(Ah + r1 * PST + ko + 8 + 2 * tig);
                al[mf][0] = *(const uint32_t*)(Al + r0 * PST + ko + 2 * tig);
                al[mf][1] = *(const uint32_t*)(Al + r1 * PST + ko + 2 * tig);
                al[mf][2] = *(const uint32_t*)(Al + r0 * PST + ko + 8 + 2 * tig);
                al[mf][3] = *(const uint32_t*)(Al + r1 * PST + ko + 8 + 2 * tig);
            }
            uint32_t bh[8][2], bl[8][2];
#pragma unroll
            for (int nf = 0; nf < 8; nf++) {
                const int n = (wn << 6) + (nf << 3) + gid;
                bh[nf][0] = *(const uint32_t*)(Bh + n * PST + ko + 2 * tig);
                bh[nf][1] = *(const uint32_t*)(Bh + n * PST + ko + 8 + 2 * tig);
                bl[nf][0] = *(const uint32_t*)(Bl + n * PST + ko + 2 * tig);
                bl[nf][1] = *(const uint32_t*)(Bl + n * PST + ko + 8 + 2 * tig);
            }
#pragma unroll
            for (int mf = 0; mf < 4; mf++)
#pragma unroll
                for (int nf = 0; nf < 8; nf++) {
                    mma16(acc[mf][nf], ah[mf], bh[nf]);
                    mma16(acc[mf][nf], ah[mf], bl[nf]);
                    mma16(acc[mf][nf], al[mf], bh[nf]);
                }
        }
    };

    const int KT = CC >> 5;  // 64
    load_tile(0, 0); CP_COMMIT();
    load_tile(1, 1); CP_COMMIT();
    for (int kt = 0; kt < KT; kt++) {
        CP_WAIT(1);
        __syncthreads();
        compute(kt % 3);
        if (kt + 2 < KT) load_tile((kt + 2) % 3, kt + 2);
        CP_COMMIT();
    }

#pragma unroll
    for (int mf = 0; mf < 4; mf++) {
        const int r = m0 + (wm << 6) + (mf << 4) + gid;
#pragma unroll
        for (int nf = 0; nf < 8; nf++) {
            const int col = (wn << 6) + (nf << 3) + (tig << 1);
            const float b0 = bias[col], b1 = bias[col + 1];
            float v0 = acc[mf][nf][0] + b0, v1 = acc[mf][nf][1] + b1;
            float v2 = acc[mf][nf][2] + b0, v3 = acc[mf][nf][3] + b1;
            bf16 h0, l0, h1, l1, h2, l2, h3, l3;
            split_bf(v0, h0, l0); split_bf(v1, h1, l1);
            split_bf(v2, h2, l2); split_bf(v3, h3, l3);
            *(bf162*)&oh[(size_t)r * DD + col]       = bf162(h0, h1);
            *(bf162*)&oh[(size_t)(r + 8) * DD + col] = bf162(h2, h3);
            *(bf162*)&ol[(size_t)r * DD + col]       = bf162(l0, l1);
            *(bf162*)&ol[(size_t)(r + 8) * DD + col] = bf162(l2, l3);
        }
    }
}

// ===========================================================================
// scores: S = qh.kh + qh.kl + ql.kh (bf16x3 pure-MMA)
// CTA 128x128, 8 warps 4m x 2n, warp 32x64, k-tile 32 (KT=8), 3-stage.
// grid: x = j-tile (18), y = i-tile (18), z = dir*4 + b (8)
// ===========================================================================
#define SC_STAGE_U 20480   // 4 regions * 128 rows * 40 units

__global__ void __launch_bounds__(256) scores_bf16_kernel(
    const bf16* __restrict__ qh_g, const bf16* __restrict__ ql_g,
    const bf16* __restrict__ kh_g, const bf16* __restrict__ kl_g,
    float* __restrict__ Sb)
{
    extern __shared__ bf16 smb[];
    const size_t z = blockIdx.z;
    const bf16* qh = qh_g + z * NN * DD;
    const bf16* ql = ql_g + z * NN * DD;
    const bf16* kh = kh_g + z * NN * DD;
    const bf16* kl = kl_g + z * NN * DD;
    float* S = Sb + z * NN * NN;
    const int i0 = blockIdx.y << 7;
    const int j0 = blockIdx.x << 7;

    const int tid = threadIdx.x, wid = tid >> 5, lane = tid & 31;
    const int wm = wid >> 1, wn = wid & 1;
    const int gid = lane >> 2, tig = lane & 3;

    float acc[2][8][4];
#pragma unroll
    for (int i = 0; i < 2; i++)
#pragma unroll
        for (int j = 0; j < 8; j++)
#pragma unroll
            for (int e = 0; e < 4; e++) acc[i][j][e] = 0.f;

    auto load_tile = [&](int s, int kt) {
        bf16* st = smb + (size_t)s * SC_STAGE_U;
        const int kb = kt << 5;
#pragma unroll
        for (int i = 0; i < 8; i++) {
            int idx = tid + (i << 8);
            int row = idx >> 2, ch = idx & 3;
            const bf16* sp;
            uint32_t dst;
            if (row < 128) {
                sp = qh + (size_t)(i0 + row) * DD + kb + ch * 8;
                dst = smem_u32(st + row * PST + ch * 8);
            } else if (row < 256) {
                sp = ql + (size_t)(i0 + row - 128) * DD + kb + ch * 8;
                dst = smem_u32(st + 5120 + (row - 128) * PST + ch * 8);
            } else if (row < 384) {
                sp = kh + (size_t)(j0 + row - 256) * DD + kb + ch * 8;
                dst = smem_u32(st + 10240 + (row - 256) * PST + ch * 8);
            } else {
                sp = kl + (size_t)(j0 + row - 384) * DD + kb + ch * 8;
                dst = smem_u32(st + 15360 + (row - 384) * PST + ch * 8);
            }
            cp16(dst, sp);
        }
    };

    auto compute = [&](int s) {
        const bf16* st = smb + (size_t)s * SC_STAGE_U;
        const bf16* Ah = st;
        const bf16* Al = st + 5120;
        const bf16* Bh = st + 10240;
        const bf16* Bl = st + 15360;
#pragma unroll
        for (int ks = 0; ks < 2; ks++) {
            const int ko = ks << 4;
            uint32_t ah[2][4], al[2][4];
#pragma unroll
            for (int mf = 0; mf < 2; mf++) {
                const int r0 = (wm << 5) + (mf << 4) + gid, r1 = r0 + 8;
                ah[mf][0] = *(const uint32_t*)(Ah + r0 * PST + ko + 2 * tig);
                ah[mf][1] = *(const uint32_t*)(Ah + r1 * PST + ko + 2 * tig);
                ah[mf][2] = *(const uint32_t*)(Ah + r0 * PST + ko + 8 + 2 * tig);
                ah[mf][3] = *(const uint32_t*)(Ah + r1 * PST + ko + 8 + 2 * tig);
                al[mf][0] = *(const uint32_t*)(Al + r0 * PST + ko + 2 * tig);
                al[mf][1] = *(const uint32_t*)(Al + r1 * PST + ko + 2 * tig);
                al[mf][2] = *(const uint32_t*)(Al + r0 * PST + ko + 8 + 2 * tig);
                al[mf][3] = *(const uint32_t*)(Al + r1 * PST + ko + 8 + 2 * tig);
            }
            uint32_t bh[8][2], bl[8][2];
#pragma unroll
            for (int nf = 0; nf < 8; nf++) {
                const int n = (wn << 6) + (nf << 3) + gid;
                bh[nf][0] = *(const uint32_t*)(Bh + n * PST + ko + 2 * tig);
                bh[nf][1] = *(const uint32_t*)(Bh + n * PST + ko + 8 + 2 * tig);
                bl[nf][0] = *(const uint32_t*)(Bl + n * PST + ko + 2 * tig);
                bl[nf][1] = *(const uint32_t*)(Bl + n * PST + ko + 8 + 2 * tig);
            }
#pragma unroll
            for (int mf = 0; mf < 2; mf++)
#pragma unroll
                for (int nf = 0; nf < 8; nf++) {
                    mma16(acc[mf][nf], ah[mf], bh[nf]);
                    mma16(acc[mf][nf], ah[mf], bl[nf]);
                    mma16(acc[mf][nf], al[mf], bh[nf]);
                }
        }
    };

    const int KT = DD >> 5;  // 8
    load_tile(0, 0); CP_COMMIT();
    load_tile(1, 1); CP_COMMIT();
    for (int kt = 0; kt < KT; kt++) {
        CP_WAIT(1);
        __syncthreads();
        compute(kt % 3);
        if (kt + 2 < KT) load_tile((kt + 2) % 3, kt + 2);
        CP_COMMIT();
    }

#pragma unroll
    for (int mf = 0; mf < 2; mf++) {
        const int r = i0 + (wm << 5) + (mf << 4) + gid;
#pragma unroll
        for (int nf = 0; nf < 8; nf++) {
            const int col = j0 + (wn << 6) + (nf << 3) + (tig << 1);
            *(float2*)&S[(size_t)r * NN + col]       = make_float2(acc[mf][nf][0], acc[mf][nf][1]);
            *(float2*)&S[(size_t)(r + 8) * NN + col] = make_float2(acc[mf][nf][2], acc[mf][nf][3]);
        }
    }
}

// ===========================================================================
// av: O[c,n] = sum_m V[c,m] * attn[n,m]  (tf32 single, unchanged from R5)
// ===========================================================================
#define ST32 36
#define AV_STAGE 13824

__global__ void __launch_bounds__(256) av_mma_kernel(
    const float* __restrict__ L, const float* __restrict__ R,
    const float* __restrict__ attnb, float* __restrict__ out)
{
    extern __shared__ float sm[];
    const int z = blockIdx.z, dir = z >> 2, b = z & 3;
    const float* V  = (dir ? L : R) + (size_t)b * CC * NN;
    const float* At = attnb + (size_t)z * NN * NN;
    float* outb = out + ((size_t)(dir ? BB : 0) + b) * 2 * CC * NN + (size_t)CC * NN;
    const int c0r = blockIdx.y << 7;
    const int n0  = blockIdx.x << 8;

    const int tid = threadIdx.x, wid = tid >> 5, lane = tid & 31;
    const int wm = wid >> 2, wn = wid & 3;
    const int gid = lane >> 2, tig = lane & 3;

    float acc[4][8][4];
#pragma unroll
    for (int i = 0; i < 4; i++)
#pragma unroll
        for (int j = 0; j < 8; j++)
#pragma unroll
            for (int e = 0; e < 4; e++) acc[i][j][e] = 0.f;

    auto load_tile = [&](int s, int kt) {
        float* As  = sm + s * AV_STAGE;
        float* Bs2 = As + 128 * ST32;
#pragma unroll
        for (int i = 0; i < 4; i++) {
            int idx = tid + (i << 8);
            int row = idx >> 3, g = idx & 7;
            cp16(smem_u32(&As[row * ST32 + (g << 2)]),
                 V + (size_t)(c0r + row) * NN + (kt << 5) + (g << 2));
        }
#pragma unroll
        for (int i = 0; i < 8; i++) {
            int idx = tid + (i << 8);
            int row = idx >> 3, g = idx & 7;
            cp16(smem_u32(&Bs2[row * ST32 + (g << 2)]),
                 At + (size_t)(n0 + row) * NN + (kt << 5) + (g << 2));
        }
    };

    auto ldfrag = [&](const float* As, const float* Bs2, int ks,
                      uint32_t a[4][4], uint32_t bf[8][2]) {
        const int kb = ks << 3;
#pragma unroll
        for (int mf = 0; mf < 4; mf++) {
            const int r0 = (wm << 6) + (mf << 4) + gid, r1 = r0 + 8;
            a[mf][0] = __float_as_uint(As[r0 * ST32 + kb + tig]);
            a[mf][1] = __float_as_uint(As[r1 * ST32 + kb + tig]);
            a[mf][2] = __float_as_uint(As[r0 * ST32 + kb + tig + 4]);
            a[mf][3] = __float_as_uint(As[r1 * ST32 + kb + tig + 4]);
        }
#pragma unroll
        for (int nf = 0; nf < 8; nf++) {
            const int n = (wn << 6) + (nf << 3) + gid;
            bf[nf][0] = __float_as_uint(Bs2[n * ST32 + kb + tig]);
            bf[nf][1] = __float_as_uint(Bs2[n * ST32 + kb + tig + 4]);
        }
    };

    auto compute = [&](int s) {
        const float* As  = sm + s * AV_STAGE;
        const float* Bs2 = As + 128 * ST32;
        uint32_t a[2][4][4], bf[2][8][2];
        ldfrag(As, Bs2, 0, a[0], bf[0]);
#pragma unroll
        for (int ks = 0; ks < 4; ks++) {
            const int cur = ks & 1, nxt = cur ^ 1;
            if (ks < 3) ldfrag(As, Bs2, ks + 1, a[nxt], bf[nxt]);
#pragma unroll
            for (int mf = 0; mf < 4; mf++)
#pragma unroll
                for (int nf = 0; nf < 8; nf++)
                    mma8(acc[mf][nf], a[cur][mf], bf[cur][nf]);
        }
    };

    const int KT = NN >> 5;  // 72
    load_tile(0, 0); CP_COMMIT();
    load_tile(1, 1); CP_COMMIT();
    for (int kt = 0; kt < KT; kt++) {
        CP_WAIT(1);
        __syncthreads();
        compute(kt % 3);
        if (kt + 2 < KT) load_tile((kt + 2) % 3, kt + 2);
        CP_COMMIT();
    }

#pragma unroll
    for (int mf = 0; mf < 4; mf++) {
        const int r = c0r + (wm << 6) + (mf << 4) + gid;
#pragma unroll
        for (int nf = 0; nf < 8; nf++) {
            const int col = n0 + (wn << 6) + (nf << 3) + (tig << 1);
            *(float2*)&outb[(size_t)r * NN + col]       = make_float2(acc[mf][nf][0], acc[mf][nf][1]);
            *(float2*)&outb[(size_t)(r + 8) * NN + col] = make_float2(acc[mf][nf][2], acc[mf][nf][3]);
        }
    }
}

// ===========================================================================
// softmax: 288 threads (9 warps), float4 IO, poly exp (no MUFU)
// ===========================================================================
__global__ void __launch_bounds__(288) softmax_kernel(float* __restrict__ Sb)
{
    float4* S4 = (float4*)(Sb + (size_t)blockIdx.x * NN);
    const int tid = threadIdx.x;
    __shared__ float red[9];
    __shared__ float bcast;

    float4 va = S4[tid], vb = S4[tid + 288];
    float m = fmaxf(fmaxf(fmaxf(va.x, va.y), fmaxf(va.z, va.w)),
                    fmaxf(fmaxf(vb.x, vb.y), fmaxf(vb.z, vb.w)));
#pragma unroll
    for (int o = 16; o; o >>= 1) m = fmaxf(m, __shfl_xor_sync(0xffffffffu, m, o));
    if ((tid & 31) == 0) red[tid >> 5] = m;
    __syncthreads();
    if (tid == 0) {
        float t = red[0];
#pragma unroll
        for (int i = 1; i < 9; i++) t = fmaxf(t, red[i]);
        bcast = t;
    }
    __syncthreads();
    m = bcast;

    va.x = fexp(va.x - m); va.y = fexp(va.y - m);
    va.z = fexp(va.z - m); va.w = fexp(va.w - m);
    vb.x = fexp(vb.x - m); vb.y = fexp(vb.y - m);
    vb.z = fexp(vb.z - m); vb.w = fexp(vb.w - m);
    float s = va.x + va.y + va.z + va.w + vb.x + vb.y + vb.z + vb.w;
#pragma unroll
    for (int o = 16; o; o >>= 1) s += __shfl_xor_sync(0xffffffffu, s, o);
    __syncthreads();
    if ((tid & 31) == 0) red[tid >> 5] = s;
    __syncthreads();
    if (tid == 0) {
        float t = 0.f;
#pragma unroll
        for (int i = 0; i < 9; i++) t += red[i];
        bcast = 1.f / t;
    }
    __syncthreads();
    const float inv = bcast;
    va.x *= inv; va.y *= inv; va.z *= inv; va.w *= inv;
    vb.x *= inv; vb.y *= inv; vb.z *= inv; vb.w *= inv;
    S4[tid] = va;
    S4[tid + 288] = vb;
}

// ---------------------------------------------------------------------------
// Copy raw features into the first C channels of each output tensor.
// ---------------------------------------------------------------------------
__global__ void __launch_bounds__(256) copy_kernel(
    const float4* __restrict__ L, const float4* __restrict__ R,
    float4* __restrict__ out)
{
    const size_t total = (size_t)BB * CC * NN / 4;
    size_t i = (size_t)blockIdx.x * 256 + threadIdx.x;
    if (i >= total) return;
    const size_t per_b = (size_t)CC * NN / 4;
    const size_t b = i / per_b;
    const size_t rem = i - b * per_b;
    const size_t dst = b * ((size_t)2 * CC * NN / 4) + rem;
    out[dst] = L[i];
    out[dst + (size_t)BB * 2 * CC * NN / 4] = R[i];
}

// ---------------------------------------------------------------------------
extern "C" void kernel_launch(void* const* d_in, const int* in_sizes, int n_in,
                              void* d_out, int out_size)
{
    const float* L  = (const float*)d_in[0];
    const float* R  = (const float*)d_in[1];
    const float* wq = (const float*)d_in[2];
    const float* bq = (const float*)d_in[3];
    const float* wr = (const float*)d_in[4];
    const float* br = (const float*)d_in[5];
    float* out = (float*)d_out;

    bf16 *xh, *xl, *wh, *wl, *qh, *ql, *kh, *kl;
    float* attn;
    cudaGetSymbolAddress((void**)&xh, g_xh);
    cudaGetSymbolAddress((void**)&xl, g_xl);
    cudaGetSymbolAddress((void**)&wh, g_wh);
    cudaGetSymbolAddress((void**)&wl, g_wl);
    cudaGetSymbolAddress((void**)&qh, g_qh);
    cudaGetSymbolAddress((void**)&ql, g_ql);
    cudaGetSymbolAddress((void**)&kh, g_kh);
    cudaGetSymbolAddress((void**)&kl, g_kl);
    cudaGetSymbolAddress((void**)&attn, g_attn);

    cudaFuncSetAttribute(proj_bf16_kernel, cudaFuncAttributeMaxDynamicSharedMemorySize,
                         3 * PROJ_STAGE_U * 2);
    cudaFuncSetAttribute(scores_bf16_kernel, cudaFuncAttributeMaxDynamicSharedMemorySize,
                         3 * SC_STAGE_U * 2);
    cudaFuncSetAttribute(av_mma_kernel, cudaFuncAttributeMaxDynamicSharedMemorySize,
                         3 * AV_STAGE * 4);

    split_w_kernel<<<2048, 256>>>(wq, wr, wh, wl);
    split_x_kernel<<<dim3(NN / 64, CC / 64, 8), 256>>>(L, R, xh, xl);
    proj_bf16_kernel<<<dim3(2, NN / 128, 8), 256, 3 * PROJ_STAGE_U * 2>>>(
        xh, xl, wh, wl, bq, br, qh, ql, kh, kl);
    scores_bf16_kernel<<<dim3(NN / 128, NN / 128, 8), 256, 3 * SC_STAGE_U * 2>>>(
        qh, ql, kh, kl, attn);
    softmax_kernel<<<2 * BB * NN, 288>>>(attn);
    av_mma_kernel<<<dim3(NN / 256, CC / 128, 8), 256, 3 * AV_STAGE * 4>>>(L, R, attn, out);

    const size_t ncpy = (size_t)BB * CC * NN / 4;
    copy_kernel<<<(unsigned)((ncpy + 255) / 256), 256>>>(
        (const float4*)L, (const float4*)R, (float4*)out);
}